// round 1
// baseline (speedup 1.0000x reference)
#include <cuda_runtime.h>
#include <cuda_fp16.h>
#include <math.h>

static constexpr int DM = 1024, NH = 8, HD = 128;
static constexpr int TQ = 8, SQ = 256, TK = 32, SK = 1024;
static constexpr int NQ = TQ * SQ;         // 2048
static constexpr int NK = TK * SK;         // 32768
static constexpr int LK = (TK / TQ) * SK;  // 4096 kv tokens per query frame
static constexpr int NB = TQ * NH;         // 64 (frame, head) batches

// ---------------- static scratch (no allocations allowed) ----------------
__device__ __half g_Wt[3][DM * DM];              // W^T fp16, [out][in]
__device__ float  g_tmpQ[(size_t)NQ * DM];       // raw projections (pre-bias, pre-rope)
__device__ float  g_tmpK[(size_t)NK * DM];
__device__ float  g_tmpV[(size_t)NK * DM];
__device__ __half g_Qh[(size_t)NQ * DM];         // [t][h][s][d]
__device__ __half g_Kh[(size_t)NK * DM];         // [tg][h][l][d]
__device__ __half g_VhT[(size_t)NK * DM];        // [tg][h][d][l]  (transposed for B operand)
__device__ float  g_S[(size_t)NB * SQ * LK];     // scores
__device__ __half g_P[(size_t)NB * SQ * LK];     // softmax probs (fp16)

__constant__ int c_tmap[8] = {0, 4, 8, 13, 17, 22, 26, 31};  // linspace(0,31,8).astype(int)

template<int S> __device__ __forceinline__ void* sel_ptr() {
  if constexpr (S == 0) return (void*)g_Wt[0];
  else if constexpr (S == 1) return (void*)g_Wt[1];
  else if constexpr (S == 2) return (void*)g_Wt[2];
  else if constexpr (S == 3) return (void*)g_tmpQ;
  else if constexpr (S == 4) return (void*)g_tmpK;
  else if constexpr (S == 5) return (void*)g_tmpV;
  else if constexpr (S == 6) return (void*)g_Qh;
  else if constexpr (S == 7) return (void*)g_Kh;
  else if constexpr (S == 8) return (void*)g_VhT;
  else if constexpr (S == 9) return (void*)g_S;
  else if constexpr (S == 10) return (void*)g_P;
  else return nullptr;
}

// ---------------- mma.sync m16n8k16 fp16 -> fp32 ----------------
__device__ __forceinline__ void mma16816(float d[4], const unsigned a[4], const unsigned b[2]) {
  asm volatile(
      "mma.sync.aligned.m16n8k16.row.col.f32.f16.f16.f32 "
      "{%0,%1,%2,%3},{%4,%5,%6,%7},{%8,%9},{%0,%1,%2,%3};\n"
      : "+f"(d[0]), "+f"(d[1]), "+f"(d[2]), "+f"(d[3])
      : "r"(a[0]), "r"(a[1]), "r"(a[2]), "r"(a[3]), "r"(b[0]), "r"(b[1]));
}

// ---------------- generic fp16 GEMM: C(MxN) = A(MxK,row) * B(NxK,"col")^T ----------------
// tile_n = blockIdx.x (fast-varying so blocks sharing an A row-block are adjacent)
// tile_m = blockIdx.y, batch = blockIdx.z
template<bool A_HALF, bool OUT_ATTN, int ASEL, int BSEL, int CSEL>
__global__ void __launch_bounds__(256) k_gemm(const void* __restrict__ Aext,
                                              float* __restrict__ Cext,
                                              int N, int K, long sA, long sB, long sC,
                                              float scale) {
  constexpr int BM = 128, BN = 64, BK = 64;
  __shared__ __half As[BM][BK + 8];
  __shared__ __half Bs[BN][BK + 8];

  const int bz = blockIdx.z;
  const void* Abase = (ASEL < 0) ? Aext : sel_ptr<ASEL>();
  const __half* Bp = (const __half*)sel_ptr<BSEL>() + (size_t)bz * sB;
  float* Cbase = (CSEL < 0) ? Cext : (float*)sel_ptr<CSEL>();
  float* Cp;
  int ldc;
  if constexpr (OUT_ATTN) {  // d_out[(t*SQ+s)*DM + h*HD + d], bz = t*NH + h
    Cp = Cbase + (size_t)(bz >> 3) * SQ * DM + (size_t)(bz & 7) * HD;
    ldc = DM;
  } else {
    Cp = Cbase + (size_t)bz * sC;
    ldc = N;
  }

  const size_t bm = (size_t)blockIdx.y * BM;
  const size_t bn = (size_t)blockIdx.x * BN;
  const int tid = threadIdx.x;
  const int lane = tid & 31, warp = tid >> 5;
  const int wm = warp >> 1, wn = warp & 1;  // 4x2 warp grid, 32x32 warp tiles

  const __half* Ah = nullptr;
  const float* Af = nullptr;
  if constexpr (A_HALF) Ah = (const __half*)Abase + (size_t)bz * sA;
  else                  Af = (const float*)Abase;

  float acc[2][4][4];
#pragma unroll
  for (int mi = 0; mi < 2; mi++)
#pragma unroll
    for (int ni = 0; ni < 4; ni++)
#pragma unroll
      for (int e = 0; e < 4; e++) acc[mi][ni][e] = 0.f;

  for (int k0 = 0; k0 < K; k0 += BK) {
    if constexpr (A_HALF) {
#pragma unroll
      for (int it = 0; it < 4; it++) {
        int idx = tid + it * 256;  // 1024 x (8-half int4)
        int r = idx >> 3, c = (idx & 7) * 8;
        *(int4*)&As[r][c] = *(const int4*)&Ah[(bm + r) * (size_t)K + k0 + c];
      }
    } else {
#pragma unroll
      for (int it = 0; it < 8; it++) {
        int idx = tid + it * 256;  // 2048 float4
        int r = idx >> 4, c = (idx & 15) * 4;
        float4 f = *(const float4*)&Af[(bm + r) * (size_t)K + k0 + c];
        *(half2*)&As[r][c]     = __floats2half2_rn(f.x, f.y);
        *(half2*)&As[r][c + 2] = __floats2half2_rn(f.z, f.w);
      }
    }
#pragma unroll
    for (int it = 0; it < 2; it++) {
      int idx = tid + it * 256;  // 512 x (8-half int4)
      int r = idx >> 3, c = (idx & 7) * 8;
      *(int4*)&Bs[r][c] = *(const int4*)&Bp[(bn + r) * (size_t)K + k0 + c];
    }
    __syncthreads();

#pragma unroll
    for (int kk = 0; kk < BK; kk += 16) {
      unsigned a[2][4], b[4][2];
      int ar = wm * 32 + (lane >> 2);
      int ac = kk + (lane & 3) * 2;
#pragma unroll
      for (int mi = 0; mi < 2; mi++) {
        int r = ar + mi * 16;
        a[mi][0] = *(const unsigned*)&As[r][ac];
        a[mi][1] = *(const unsigned*)&As[r + 8][ac];
        a[mi][2] = *(const unsigned*)&As[r][ac + 8];
        a[mi][3] = *(const unsigned*)&As[r + 8][ac + 8];
      }
#pragma unroll
      for (int ni = 0; ni < 4; ni++) {
        int n = wn * 32 + ni * 8 + (lane >> 2);
        b[ni][0] = *(const unsigned*)&Bs[n][ac];
        b[ni][1] = *(const unsigned*)&Bs[n][ac + 8];
      }
#pragma unroll
      for (int mi = 0; mi < 2; mi++)
#pragma unroll
        for (int ni = 0; ni < 4; ni++) mma16816(acc[mi][ni], a[mi], b[ni]);
    }
    __syncthreads();
  }

#pragma unroll
  for (int mi = 0; mi < 2; mi++)
#pragma unroll
    for (int ni = 0; ni < 4; ni++) {
      size_t r = bm + wm * 32 + mi * 16 + (lane >> 2);
      size_t c = bn + wn * 32 + ni * 8 + (lane & 3) * 2;
      float2 v0 = make_float2(acc[mi][ni][0] * scale, acc[mi][ni][1] * scale);
      float2 v1 = make_float2(acc[mi][ni][2] * scale, acc[mi][ni][3] * scale);
      *(float2*)&Cp[r * (size_t)ldc + c] = v0;
      *(float2*)&Cp[(r + 8) * (size_t)ldc + c] = v1;
    }
}

// ---------------- weight transpose+cast ----------------
__global__ void k_prep_w(const float* __restrict__ Wq, const float* __restrict__ Wk,
                         const float* __restrict__ Wv) {
  int i = blockIdx.x * blockDim.x + threadIdx.x;
  if (i >= DM * DM) return;
  int o = i / DM, in = i % DM;
  int src = in * DM + o;  // Wt[o][in] = W[in][o]
  g_Wt[0][i] = __float2half(Wq[src]);
  g_Wt[1][i] = __float2half(Wk[src]);
  g_Wt[2][i] = __float2half(Wv[src]);
}

// ---------------- mrope + bias + cast to head-major fp16 ----------------
template<bool IS_Q>
__global__ void k_rope(const float* __restrict__ bias) {
  const float* __restrict__ tmp = IS_Q ? g_tmpQ : g_tmpK;
  __half* __restrict__ out = IS_Q ? g_Qh : g_Kh;
  const long total = (long)(IS_Q ? NQ : NK) * NH * 64;
  long idx = (long)blockIdx.x * blockDim.x + threadIdx.x;
  if (idx >= total) return;
  int j = (int)(idx & 63);        // rotary pair index 0..63
  int h = (int)((idx >> 6) & 7);  // head
  long n = idx >> 9;              // token
  int p;
  if (IS_Q) {
    int t = (int)(n >> 8), rem = (int)(n & 255);
    int p0 = c_tmap[t], p1 = 2 * (rem >> 4) + 1, p2 = 2 * (rem & 15) + 1;
    p = (j < 16) ? p0 : ((j < 40) ? p1 : p2);  // mrope_section [16,24,24]
  } else {
    int p0 = (int)(n >> 10), p1 = (int)((n >> 5) & 31), p2 = (int)(n & 31);
    p = (j < 16) ? p0 : ((j < 40) ? p1 : p2);
  }
  float invf = expf(-(float)j * (9.210340371976184f / 64.0f));  // 10000^(-j/64)
  float ang = (float)p * invf;
  ang -= 6.283185307179586f * floorf(ang * 0.15915494309189535f);  // safe range for sincos
  float sv, cv;
  sincosf(ang, &sv, &cv);
  int col = h * HD + j;
  float x0 = tmp[n * DM + col] + bias[col];
  float x1 = tmp[n * DM + col + 64] + bias[col + 64];
  size_t base;
  if (IS_Q) {
    size_t t = n >> 8, s = n & 255;
    base = ((t * NH + h) * (size_t)SQ + s) * HD;
  } else {
    size_t tg = n >> 12, l = n & 4095;
    base = ((tg * NH + h) * (size_t)LK + l) * HD;
  }
  out[base + j]      = __float2half(x0 * cv - x1 * sv);
  out[base + j + 64] = __float2half(x1 * cv + x0 * sv);
}

// ---------------- V: bias + cast + transpose to [z][d][l] ----------------
__global__ void k_vfin(const float* __restrict__ bias) {
  __shared__ float ts[32][33];
  int z = blockIdx.z;
  int tg = z >> 3, h = z & 7;
  int l0 = blockIdx.x * 32, d0 = blockIdx.y * 32;
  int lx = threadIdx.x, ly = threadIdx.y;  // (32, 8)
#pragma unroll
  for (int i = 0; i < 32; i += 8) {
    int l = l0 + ly + i, d = d0 + lx;
    ts[ly + i][lx] = g_tmpV[((size_t)tg * 4096 + l) * DM + h * HD + d] + bias[h * HD + d];
  }
  __syncthreads();
#pragma unroll
  for (int i = 0; i < 32; i += 8) {
    int d = d0 + ly + i, l = l0 + lx;
    g_VhT[((size_t)z * HD + d) * LK + l] = __float2half(ts[lx][ly + i]);
  }
}

// ---------------- row softmax over 4096, fp32 -> fp16 ----------------
__global__ void __launch_bounds__(256) k_softmax() {
  __shared__ float red[8];
  const size_t row = blockIdx.x;
  const float* s = g_S + row * LK;
  __half* p = g_P + row * LK;
  int tid = threadIdx.x;
  float vv[16];
  float m = -3.0e38f;
#pragma unroll
  for (int i = 0; i < 16; i++) {
    vv[i] = s[tid + i * 256];
    m = fmaxf(m, vv[i]);
  }
#pragma unroll
  for (int o = 16; o > 0; o >>= 1) m = fmaxf(m, __shfl_xor_sync(0xffffffffu, m, o));
  if ((tid & 31) == 0) red[tid >> 5] = m;
  __syncthreads();
  float mm = red[0];
#pragma unroll
  for (int i = 1; i < 8; i++) mm = fmaxf(mm, red[i]);
  __syncthreads();
  float sum = 0.f;
#pragma unroll
  for (int i = 0; i < 16; i++) {
    vv[i] = expf(vv[i] - mm);
    sum += vv[i];
  }
#pragma unroll
  for (int o = 16; o > 0; o >>= 1) sum += __shfl_xor_sync(0xffffffffu, sum, o);
  if ((tid & 31) == 0) red[tid >> 5] = sum;
  __syncthreads();
  float tot = 0.f;
#pragma unroll
  for (int i = 0; i < 8; i++) tot += red[i];
  float inv = 1.0f / tot;
#pragma unroll
  for (int i = 0; i < 16; i++) p[tid + i * 256] = __float2half(vv[i] * inv);
}

// ---------------- launch ----------------
extern "C" void kernel_launch(void* const* d_in, const int* in_sizes, int n_in,
                              void* d_out, int out_size) {
  const float* q  = (const float*)d_in[0];
  const float* k  = (const float*)d_in[1];
  const float* v  = (const float*)d_in[2];
  const float* Wq = (const float*)d_in[3];
  const float* bq = (const float*)d_in[4];
  const float* Wk = (const float*)d_in[5];
  const float* bk = (const float*)d_in[6];
  const float* Wv = (const float*)d_in[7];
  const float* bv = (const float*)d_in[8];
  float* out = (float*)d_out;
  (void)in_sizes; (void)n_in; (void)out_size;

  k_prep_w<<<(DM * DM + 255) / 256, 256>>>(Wq, Wk, Wv);

  // projections -> fp32 scratch (grid.x = n-tiles so A row-block readers are adjacent)
  k_gemm<false, false, -1, 0, 3><<<dim3(DM / 64, NQ / 128, 1), 256>>>(q, nullptr, DM, DM, 0, 0, 0, 1.0f);
  k_gemm<false, false, -1, 1, 4><<<dim3(DM / 64, NK / 128, 1), 256>>>(k, nullptr, DM, DM, 0, 0, 0, 1.0f);
  k_gemm<false, false, -1, 2, 5><<<dim3(DM / 64, NK / 128, 1), 256>>>(v, nullptr, DM, DM, 0, 0, 0, 1.0f);

  // bias + rope + relayout
  k_rope<true><<<(NQ * NH * 64) / 256, 256>>>(bq);
  k_rope<false><<<(NK * NH * 64) / 256, 256>>>(bk);
  k_vfin<<<dim3(LK / 32, HD / 32, NB), dim3(32, 8)>>>(bv);

  // scores = Q K^T / sqrt(HD)
  k_gemm<true, false, 6, 7, 9><<<dim3(LK / 64, SQ / 128, NB), 256>>>(
      nullptr, nullptr, LK, HD, (long)SQ * HD, (long)LK * HD, (long)SQ * LK,
      0.08838834764831845f);

  k_softmax<<<NB * SQ, 256>>>();

  // out = P V  (epilogue writes d_out layout directly)
  k_gemm<true, true, 10, 8, -1><<<dim3(HD / 64, SQ / 128, NB), 256>>>(
      nullptr, out, HD, LK, (long)SQ * LK, (long)HD * LK, 0, 1.0f);
}

// round 5
// speedup vs baseline: 1.4702x; 1.4702x over previous
#include <cuda_runtime.h>
#include <cuda_fp16.h>
#include <math.h>

static constexpr int DM = 1024, NH = 8, HD = 128;
static constexpr int TQ = 8, SQ = 256, TK = 32, SK = 1024;
static constexpr int NQ = TQ * SQ;         // 2048
static constexpr int NK = TK * SK;         // 32768
static constexpr int LK = (TK / TQ) * SK;  // 4096 kv tokens per query frame
static constexpr int NB = TQ * NH;         // 64 (frame, head) batches

// ---------------- static scratch (no allocations allowed) ----------------
__device__ __half g_Wt[3][DM * DM];              // W^T fp16, [out][in]
__device__ __half g_Aq[(size_t)NQ * DM];         // fp16 copies of inputs (cp.async-able)
__device__ __half g_Ak[(size_t)NK * DM];
__device__ __half g_Av[(size_t)NK * DM];
__device__ float  g_tmpQ[(size_t)NQ * DM];       // raw projections (pre-bias, pre-rope)
__device__ float  g_tmpK[(size_t)NK * DM];
__device__ float  g_tmpV[(size_t)NK * DM];
__device__ __half g_Qh[(size_t)NQ * DM];         // [t][h][s][d]
__device__ __half g_Kh[(size_t)NK * DM];         // [tg][h][l][d]
__device__ __half g_VhT[(size_t)NK * DM];        // [tg][h][d][l]
__device__ float  g_S[(size_t)NB * SQ * LK];     // scores
__device__ __half g_P[(size_t)NB * SQ * LK];     // softmax probs (fp16)

__constant__ int c_tmap[8] = {0, 4, 8, 13, 17, 22, 26, 31};

template<int S> __device__ __forceinline__ void* sel_ptr() {
  if constexpr (S == 0) return (void*)g_Wt[0];
  else if constexpr (S == 1) return (void*)g_Wt[1];
  else if constexpr (S == 2) return (void*)g_Wt[2];
  else if constexpr (S == 3) return (void*)g_tmpQ;
  else if constexpr (S == 4) return (void*)g_tmpK;
  else if constexpr (S == 5) return (void*)g_tmpV;
  else if constexpr (S == 6) return (void*)g_Qh;
  else if constexpr (S == 7) return (void*)g_Kh;
  else if constexpr (S == 8) return (void*)g_VhT;
  else if constexpr (S == 9) return (void*)g_S;
  else if constexpr (S == 10) return (void*)g_P;
  else if constexpr (S == 11) return (void*)g_Aq;
  else if constexpr (S == 12) return (void*)g_Ak;
  else if constexpr (S == 13) return (void*)g_Av;
  else return nullptr;
}

// ---------------- primitives ----------------
__device__ __forceinline__ void mma16816(float d[4], const unsigned a[4], const unsigned b[2]) {
  asm volatile(
      "mma.sync.aligned.m16n8k16.row.col.f32.f16.f16.f32 "
      "{%0,%1,%2,%3},{%4,%5,%6,%7},{%8,%9},{%0,%1,%2,%3};\n"
      : "+f"(d[0]), "+f"(d[1]), "+f"(d[2]), "+f"(d[3])
      : "r"(a[0]), "r"(a[1]), "r"(a[2]), "r"(a[3]), "r"(b[0]), "r"(b[1]));
}

__device__ __forceinline__ void cp16(void* smem_dst, const void* gmem_src) {
  unsigned d = (unsigned)__cvta_generic_to_shared(smem_dst);
  asm volatile("cp.async.cg.shared.global [%0], [%1], 16;\n" :: "r"(d), "l"(gmem_src));
}
__device__ __forceinline__ void cp_commit() { asm volatile("cp.async.commit_group;\n"); }
template<int N> __device__ __forceinline__ void cp_wait() {
  asm volatile("cp.async.wait_group %0;\n" :: "n"(N));
}

// ---------------- pipelined fp16 GEMM: C(MxN) = A(MxK,row) * B(NxK)^T ----------------
// blockIdx.x = n-tile (fast), blockIdx.y = m-tile, blockIdx.z = batch
template<bool OUT_ATTN, int ASEL, int BSEL, int CSEL>
__global__ void __launch_bounds__(256, 2) k_gemm2(float* __restrict__ Cext,
                                                  int K, long sA, long sB, long sC,
                                                  float scale) {
  constexpr int BM = 128, BN = 128, BK = 32;
  __shared__ __half As[2][BM][BK + 8];
  __shared__ __half Bs[2][BN][BK + 8];

  const int bz = blockIdx.z;
  const __half* Ap = (const __half*)sel_ptr<ASEL>() + (size_t)bz * sA;
  const __half* Bp = (const __half*)sel_ptr<BSEL>() + (size_t)bz * sB;
  float* Cbase = (CSEL < 0) ? Cext : (float*)sel_ptr<CSEL>();
  float* Cp;
  int ldc;
  if constexpr (OUT_ATTN) {  // d_out[(t*SQ+s)*DM + h*HD + d], bz = t*NH + h
    Cp = Cbase + (size_t)(bz >> 3) * SQ * DM + (size_t)(bz & 7) * HD;
    ldc = DM;
  } else {
    Cp = Cbase + (size_t)bz * sC;
    ldc = (CSEL == 9) ? LK : DM;
  }

  const size_t bm = (size_t)blockIdx.y * BM;
  const size_t bn = (size_t)blockIdx.x * BN;
  const int tid = threadIdx.x;
  const int lane = tid & 31, warp = tid >> 5;
  const int wm = warp & 1, wn = warp >> 1;  // 2x4 warp grid, 64x32 warp tiles

  const int NIT = K / BK;

  auto load_stage = [&](int it, int s) {
    const int k0 = it * BK;
#pragma unroll
    for (int i = 0; i < 2; i++) {
      int idx = tid + i * 256;       // 512 int4 for A
      int r = idx >> 2;
      int c = (idx & 3) * 8;
      cp16(&As[s][r][c], Ap + (bm + r) * (size_t)K + k0 + c);
    }
#pragma unroll
    for (int i = 0; i < 2; i++) {
      int idx = tid + i * 256;       // 512 int4 for B
      int r = idx >> 2;
      int c = (idx & 3) * 8;
      cp16(&Bs[s][r][c], Bp + (bn + r) * (size_t)K + k0 + c);
    }
    cp_commit();
  };

  float acc[4][4][4];
#pragma unroll
  for (int mi = 0; mi < 4; mi++)
#pragma unroll
    for (int ni = 0; ni < 4; ni++)
#pragma unroll
      for (int e = 0; e < 4; e++) acc[mi][ni][e] = 0.f;

  load_stage(0, 0);
  if (NIT > 1) load_stage(1, 1);

  for (int it = 0; it < NIT; ++it) {
    if (it + 1 < NIT) cp_wait<1>(); else cp_wait<0>();
    __syncthreads();
    const int s = it & 1;
#pragma unroll
    for (int kk = 0; kk < BK; kk += 16) {
      unsigned a[4][4], b[4][2];
      const int ar = wm * 64 + (lane >> 2);
      const int ac = kk + (lane & 3) * 2;
#pragma unroll
      for (int mi = 0; mi < 4; mi++) {
        int r = ar + mi * 16;
        a[mi][0] = *(const unsigned*)&As[s][r][ac];
        a[mi][1] = *(const unsigned*)&As[s][r + 8][ac];
        a[mi][2] = *(const unsigned*)&As[s][r][ac + 8];
        a[mi][3] = *(const unsigned*)&As[s][r + 8][ac + 8];
      }
#pragma unroll
      for (int ni = 0; ni < 4; ni++) {
        int n = wn * 32 + ni * 8 + (lane >> 2);
        b[ni][0] = *(const unsigned*)&Bs[s][n][ac];
        b[ni][1] = *(const unsigned*)&Bs[s][n][ac + 8];
      }
#pragma unroll
      for (int mi = 0; mi < 4; mi++)
#pragma unroll
        for (int ni = 0; ni < 4; ni++) mma16816(acc[mi][ni], a[mi], b[ni]);
    }
    __syncthreads();
    if (it + 2 < NIT) load_stage(it + 2, s);
  }

#pragma unroll
  for (int mi = 0; mi < 4; mi++)
#pragma unroll
    for (int ni = 0; ni < 4; ni++) {
      size_t r = bm + wm * 64 + mi * 16 + (lane >> 2);
      size_t c = bn + wn * 32 + ni * 8 + (lane & 3) * 2;
      float2 v0 = make_float2(acc[mi][ni][0] * scale, acc[mi][ni][1] * scale);
      float2 v1 = make_float2(acc[mi][ni][2] * scale, acc[mi][ni][3] * scale);
      *(float2*)&Cp[r * (size_t)ldc + c] = v0;
      *(float2*)&Cp[(r + 8) * (size_t)ldc + c] = v1;
    }
}

// ---------------- input cast fp32 -> fp16 (8 elems/thread) ----------------
// Destination resolved DEVICE-SIDE via sel_ptr (a __device__ symbol passed as a
// host-side kernel argument is NOT a valid device pointer — round-2 failure).
template<int DSEL>
__global__ void k_cast(const float* __restrict__ s) {
  __half* __restrict__ d = (__half*)sel_ptr<DSEL>();
  size_t i = ((size_t)blockIdx.x * blockDim.x + threadIdx.x) * 8;
  float4 f0 = *(const float4*)(s + i);
  float4 f1 = *(const float4*)(s + i + 4);
  __half2 h[4];
  h[0] = __floats2half2_rn(f0.x, f0.y);
  h[1] = __floats2half2_rn(f0.z, f0.w);
  h[2] = __floats2half2_rn(f1.x, f1.y);
  h[3] = __floats2half2_rn(f1.z, f1.w);
  *(int4*)(d + i) = *(const int4*)h;
}

// ---------------- weight transpose+cast ----------------
__global__ void k_prep_w(const float* __restrict__ Wq, const float* __restrict__ Wk,
                         const float* __restrict__ Wv) {
  int i = blockIdx.x * blockDim.x + threadIdx.x;
  if (i >= DM * DM) return;
  int o = i / DM, in = i % DM;
  int src = in * DM + o;
  g_Wt[0][i] = __float2half(Wq[src]);
  g_Wt[1][i] = __float2half(Wk[src]);
  g_Wt[2][i] = __float2half(Wv[src]);
}

// ---------------- mrope + bias + cast to head-major fp16 ----------------
template<bool IS_Q>
__global__ void k_rope(const float* __restrict__ bias) {
  const float* __restrict__ tmp = IS_Q ? g_tmpQ : g_tmpK;
  __half* __restrict__ out = IS_Q ? g_Qh : g_Kh;
  const long total = (long)(IS_Q ? NQ : NK) * NH * 64;
  long idx = (long)blockIdx.x * blockDim.x + threadIdx.x;
  if (idx >= total) return;
  int j = (int)(idx & 63);
  int h = (int)((idx >> 6) & 7);
  long n = idx >> 9;
  int p;
  if (IS_Q) {
    int t = (int)(n >> 8), rem = (int)(n & 255);
    int p0 = c_tmap[t], p1 = 2 * (rem >> 4) + 1, p2 = 2 * (rem & 15) + 1;
    p = (j < 16) ? p0 : ((j < 40) ? p1 : p2);
  } else {
    int p0 = (int)(n >> 10), p1 = (int)((n >> 5) & 31), p2 = (int)(n & 31);
    p = (j < 16) ? p0 : ((j < 40) ? p1 : p2);
  }
  float invf = expf(-(float)j * (9.210340371976184f / 64.0f));
  float ang = (float)p * invf;
  ang -= 6.283185307179586f * floorf(ang * 0.15915494309189535f);
  float sv, cv;
  sincosf(ang, &sv, &cv);
  int col = h * HD + j;
  float x0 = tmp[n * DM + col] + bias[col];
  float x1 = tmp[n * DM + col + 64] + bias[col + 64];
  size_t base;
  if (IS_Q) {
    size_t t = n >> 8, s = n & 255;
    base = ((t * NH + h) * (size_t)SQ + s) * HD;
  } else {
    size_t tg = n >> 12, l = n & 4095;
    base = ((tg * NH + h) * (size_t)LK + l) * HD;
  }
  out[base + j]      = __float2half(x0 * cv - x1 * sv);
  out[base + j + 64] = __float2half(x1 * cv + x0 * sv);
}

// ---------------- V: bias + cast + transpose to [z][d][l] ----------------
__global__ void k_vfin(const float* __restrict__ bias) {
  __shared__ float ts[32][33];
  int z = blockIdx.z;
  int tg = z >> 3, h = z & 7;
  int l0 = blockIdx.x * 32, d0 = blockIdx.y * 32;
  int lx = threadIdx.x, ly = threadIdx.y;  // (32, 8)
#pragma unroll
  for (int i = 0; i < 32; i += 8) {
    int l = l0 + ly + i, d = d0 + lx;
    ts[ly + i][lx] = g_tmpV[((size_t)tg * 4096 + l) * DM + h * HD + d] + bias[h * HD + d];
  }
  __syncthreads();
#pragma unroll
  for (int i = 0; i < 32; i += 8) {
    int d = d0 + ly + i, l = l0 + lx;
    g_VhT[((size_t)z * HD + d) * LK + l] = __float2half(ts[lx][ly + i]);
  }
}

// ---------------- row softmax over 4096, fp32 -> fp16 ----------------
__global__ void __launch_bounds__(256) k_softmax() {
  __shared__ float red[8];
  const size_t row = blockIdx.x;
  const float* s = g_S + row * LK;
  __half* p = g_P + row * LK;
  int tid = threadIdx.x;
  float vv[16];
  float m = -3.0e38f;
#pragma unroll
  for (int i = 0; i < 4; i++) {
    float4 f = *(const float4*)&s[(tid + i * 256) * 4];
    vv[i * 4 + 0] = f.x; vv[i * 4 + 1] = f.y; vv[i * 4 + 2] = f.z; vv[i * 4 + 3] = f.w;
    m = fmaxf(fmaxf(fmaxf(m, f.x), fmaxf(f.y, f.z)), f.w);
  }
#pragma unroll
  for (int o = 16; o > 0; o >>= 1) m = fmaxf(m, __shfl_xor_sync(0xffffffffu, m, o));
  if ((tid & 31) == 0) red[tid >> 5] = m;
  __syncthreads();
  float mm = red[0];
#pragma unroll
  for (int i = 1; i < 8; i++) mm = fmaxf(mm, red[i]);
  __syncthreads();
  float sum = 0.f;
#pragma unroll
  for (int i = 0; i < 16; i++) {
    vv[i] = expf(vv[i] - mm);
    sum += vv[i];
  }
#pragma unroll
  for (int o = 16; o > 0; o >>= 1) sum += __shfl_xor_sync(0xffffffffu, sum, o);
  if ((tid & 31) == 0) red[tid >> 5] = sum;
  __syncthreads();
  float tot = 0.f;
#pragma unroll
  for (int i = 0; i < 8; i++) tot += red[i];
  float inv = 1.0f / tot;
#pragma unroll
  for (int i = 0; i < 4; i++) {
    __half2 h0 = __floats2half2_rn(vv[i * 4 + 0] * inv, vv[i * 4 + 1] * inv);
    __half2 h1 = __floats2half2_rn(vv[i * 4 + 2] * inv, vv[i * 4 + 3] * inv);
    *(int2*)&p[(tid + i * 256) * 4] = make_int2(*(int*)&h0, *(int*)&h1);
  }
}

// ---------------- launch ----------------
extern "C" void kernel_launch(void* const* d_in, const int* in_sizes, int n_in,
                              void* d_out, int out_size) {
  const float* q  = (const float*)d_in[0];
  const float* k  = (const float*)d_in[1];
  const float* v  = (const float*)d_in[2];
  const float* Wq = (const float*)d_in[3];
  const float* bq = (const float*)d_in[4];
  const float* Wk = (const float*)d_in[5];
  const float* bk = (const float*)d_in[6];
  const float* Wv = (const float*)d_in[7];
  const float* bv = (const float*)d_in[8];
  float* out = (float*)d_out;
  (void)in_sizes; (void)n_in; (void)out_size;

  // fp32 -> fp16 casts (enables cp.async pipelined GEMMs)
  k_cast<11><<<(NQ * DM) / 2048, 256>>>(q);
  k_cast<12><<<(NK * DM) / 2048, 256>>>(k);
  k_cast<13><<<(NK * DM) / 2048, 256>>>(v);
  k_prep_w<<<(DM * DM + 255) / 256, 256>>>(Wq, Wk, Wv);

  // projections -> fp32 scratch
  k_gemm2<false, 11, 0, 3><<<dim3(DM / 128, NQ / 128, 1), 256>>>(nullptr, DM, 0, 0, 0, 1.0f);
  k_gemm2<false, 12, 1, 4><<<dim3(DM / 128, NK / 128, 1), 256>>>(nullptr, DM, 0, 0, 0, 1.0f);
  k_gemm2<false, 13, 2, 5><<<dim3(DM / 128, NK / 128, 1), 256>>>(nullptr, DM, 0, 0, 0, 1.0f);

  // bias + rope + relayout
  k_rope<true><<<(NQ * NH * 64) / 256, 256>>>(bq);
  k_rope<false><<<(NK * NH * 64) / 256, 256>>>(bk);
  k_vfin<<<dim3(LK / 32, HD / 32, NB), dim3(32, 8)>>>(bv);

  // scores = Q K^T / sqrt(HD)
  k_gemm2<false, 6, 7, 9><<<dim3(LK / 128, SQ / 128, NB), 256>>>(
      nullptr, HD, (long)SQ * HD, (long)LK * HD, (long)SQ * LK, 0.08838834764831845f);

  k_softmax<<<NB * SQ, 256>>>();

  // out = P V  (epilogue writes d_out layout directly)
  k_gemm2<true, 10, 8, -1><<<dim3(HD / 128, SQ / 128, NB), 256>>>(
      out, LK, (long)SQ * LK, (long)HD * LK, 0, 1.0f);
}

// round 6
// speedup vs baseline: 1.8117x; 1.2323x over previous
#include <cuda_runtime.h>
#include <cuda_fp16.h>
#include <math.h>

static constexpr int DM = 1024, NH = 8, HD = 128;
static constexpr int TQ = 8, SQ = 256, TK = 32, SK = 1024;
static constexpr int NQ = TQ * SQ;         // 2048
static constexpr int NK = TK * SK;         // 32768
static constexpr int LK = (TK / TQ) * SK;  // 4096 kv tokens per query frame

// ---------------- static scratch ----------------
__device__ __half g_Wt[3][DM * DM];          // W^T fp16, [out][in]
__device__ __half g_Aq[(size_t)NQ * DM];     // fp16 inputs (cp.async-able)
__device__ __half g_Ak[(size_t)NK * DM];
__device__ __half g_Av[(size_t)NK * DM];
__device__ __half g_Qh[(size_t)NQ * DM];     // [t][h][s][d] rope'd, pre-scaled by 1/sqrt(128)*log2e
__device__ __half g_Kh[(size_t)NK * DM];     // [tg][h][l][d] rope'd
__device__ __half g_VhT[(size_t)NK * DM];    // [tg][h][d][l]

__constant__ int c_tmap[8] = {0, 4, 8, 13, 17, 22, 26, 31};

template<int S> __device__ __forceinline__ __half* sel_ptr() {
  if constexpr (S == 0) return g_Wt[0];
  else if constexpr (S == 1) return g_Wt[1];
  else if constexpr (S == 2) return g_Wt[2];
  else if constexpr (S == 3) return g_Aq;
  else if constexpr (S == 4) return g_Ak;
  else if constexpr (S == 5) return g_Av;
  else if constexpr (S == 6) return g_Qh;
  else if constexpr (S == 7) return g_Kh;
  else return g_VhT;
}

// ---------------- primitives ----------------
__device__ __forceinline__ void mma16816(float d[4], const unsigned a[4], const unsigned b[2]) {
  asm volatile(
      "mma.sync.aligned.m16n8k16.row.col.f32.f16.f16.f32 "
      "{%0,%1,%2,%3},{%4,%5,%6,%7},{%8,%9},{%0,%1,%2,%3};\n"
      : "+f"(d[0]), "+f"(d[1]), "+f"(d[2]), "+f"(d[3])
      : "r"(a[0]), "r"(a[1]), "r"(a[2]), "r"(a[3]), "r"(b[0]), "r"(b[1]));
}
__device__ __forceinline__ void cp16(void* smem_dst, const void* gmem_src) {
  unsigned d = (unsigned)__cvta_generic_to_shared(smem_dst);
  asm volatile("cp.async.cg.shared.global [%0], [%1], 16;\n" :: "r"(d), "l"(gmem_src));
}
__device__ __forceinline__ void cp_commit() { asm volatile("cp.async.commit_group;\n"); }
template<int N> __device__ __forceinline__ void cp_wait() {
  asm volatile("cp.async.wait_group %0;\n" :: "n"(N));
}
__device__ __forceinline__ void ldsm4(unsigned r[4], const __half* p) {
  unsigned a = (unsigned)__cvta_generic_to_shared(p);
  asm volatile("ldmatrix.sync.aligned.m8n8.x4.shared.b16 {%0,%1,%2,%3},[%4];\n"
               : "=r"(r[0]), "=r"(r[1]), "=r"(r[2]), "=r"(r[3]) : "r"(a));
}
__device__ __forceinline__ float ex2f(float x) {
  float y; asm("ex2.approx.ftz.f32 %0, %1;" : "=f"(y) : "f"(x)); return y;
}
__device__ __forceinline__ unsigned h2ex2(unsigned x) {
  unsigned y; asm("ex2.approx.f16x2 %0, %1;" : "=r"(y) : "r"(x)); return y;
}

// ---------------- projection GEMM + fused bias/rope/layout epilogue ----------------
// C(MxN) = A(MxK,row) * B(NxK)^T ; blockIdx.x = head (n-tile of 128), blockIdx.y = m-tile
// Warp n-frag mapping puts columns j and j+64 in the SAME thread (rope pairing).
// MODE 0 = Q (head-major + rope + fold softmax scale), 1 = K (head-major + rope), 2 = V (transposed)
template<int MODE, int ASEL, int BSEL>
__global__ void __launch_bounds__(256, 2) k_gemm3(const float* __restrict__ bias) {
  constexpr int BM = 128, BN = 128, BK = 32, KD = DM;
  __shared__ __half As[2][BM][BK + 8];
  __shared__ __half Bs[2][BN][BK + 8];

  const __half* Ap = sel_ptr<ASEL>();
  const __half* Bp = sel_ptr<BSEL>();
  const size_t bm = (size_t)blockIdx.y * BM;
  const int h = blockIdx.x;
  const size_t bn = (size_t)h * BN;
  const int tid = threadIdx.x, lane = tid & 31, warp = tid >> 5;
  const int wm = warp & 1, wn = warp >> 1;  // 2x4 warps, 64x32 tiles
  const int NIT = KD / BK;

  auto load_stage = [&](int it, int s) {
    const int k0 = it * BK;
#pragma unroll
    for (int i = 0; i < 2; i++) {
      int idx = tid + i * 256; int r = idx >> 2, c = (idx & 3) * 8;
      cp16(&As[s][r][c], Ap + (bm + r) * KD + k0 + c);
    }
#pragma unroll
    for (int i = 0; i < 2; i++) {
      int idx = tid + i * 256; int r = idx >> 2, c = (idx & 3) * 8;
      cp16(&Bs[s][r][c], Bp + (bn + r) * KD + k0 + c);
    }
    cp_commit();
  };

  float acc[4][4][4];
#pragma unroll
  for (int mi = 0; mi < 4; mi++)
#pragma unroll
    for (int ni = 0; ni < 4; ni++)
#pragma unroll
      for (int e = 0; e < 4; e++) acc[mi][ni][e] = 0.f;

  load_stage(0, 0);
  load_stage(1, 1);

  for (int it = 0; it < NIT; ++it) {
    if (it + 1 < NIT) cp_wait<1>(); else cp_wait<0>();
    __syncthreads();
    const int s = it & 1;
#pragma unroll
    for (int kk = 0; kk < BK; kk += 16) {
      unsigned a[4][4], b[4][2];
      const int ar = wm * 64 + (lane >> 2);
      const int ac = kk + (lane & 3) * 2;
#pragma unroll
      for (int mi = 0; mi < 4; mi++) {
        int r = ar + mi * 16;
        a[mi][0] = *(const unsigned*)&As[s][r][ac];
        a[mi][1] = *(const unsigned*)&As[s][r + 8][ac];
        a[mi][2] = *(const unsigned*)&As[s][r][ac + 8];
        a[mi][3] = *(const unsigned*)&As[s][r + 8][ac + 8];
      }
#pragma unroll
      for (int ni = 0; ni < 4; ni++) {
        int n = (ni >> 1) * 64 + wn * 16 + (ni & 1) * 8 + (lane >> 2);
        b[ni][0] = *(const unsigned*)&Bs[s][n][ac];
        b[ni][1] = *(const unsigned*)&Bs[s][n][ac + 8];
      }
#pragma unroll
      for (int mi = 0; mi < 4; mi++)
#pragma unroll
        for (int ni = 0; ni < 4; ni++) mma16816(acc[mi][ni], a[mi], b[ni]);
    }
    __syncthreads();
    if (it + 2 < NIT) load_stage(it + 2, s);
  }

  if constexpr (MODE == 2) {
    // V: bias + cast + direct transpose to [z][d][l]
#pragma unroll
    for (int mi = 0; mi < 4; mi++)
#pragma unroll
      for (int ni = 0; ni < 4; ni++)
#pragma unroll
        for (int e = 0; e < 4; e++) {
          int token = (int)bm + wm * 64 + mi * 16 + (lane >> 2) + (e >> 1) * 8;
          int d = (ni >> 1) * 64 + wn * 16 + (ni & 1) * 8 + (lane & 3) * 2 + (e & 1);
          float val = acc[mi][ni][e] + bias[h * HD + d];
          int tg = token >> 12, l = token & 4095;
          g_VhT[((size_t)(tg * NH + h) * HD + d) * LK + l] = __float2half(val);
        }
  } else {
    constexpr float CSC = 0.08838834764831845f * 1.4426950408889634f;  // 1/sqrt(128)*log2e
#pragma unroll
    for (int mi = 0; mi < 4; mi++)
#pragma unroll
      for (int ni = 0; ni < 2; ni++)
#pragma unroll
        for (int e = 0; e < 4; e++) {
          int token = (int)bm + wm * 64 + mi * 16 + (lane >> 2) + (e >> 1) * 8;
          int j = wn * 16 + ni * 8 + (lane & 3) * 2 + (e & 1);
          float x0 = acc[mi][ni][e] + bias[h * HD + j];
          float x1 = acc[mi][ni + 2][e] + bias[h * HD + j + 64];
          int p; size_t base;
          if constexpr (MODE == 0) {
            int t = token >> 8, rem = token & 255;
            p = (j < 16) ? c_tmap[t] : (j < 40) ? 2 * (rem >> 4) + 1 : 2 * (rem & 15) + 1;
            base = ((size_t)(t * NH + h) * SQ + rem) * HD;
          } else {
            p = (j < 16) ? (token >> 10) : (j < 40) ? ((token >> 5) & 31) : (token & 31);
            base = ((size_t)((token >> 12) * NH + h) * LK + (token & 4095)) * HD;
          }
          float invf = ex2f(-(float)j * 0.20762050593046015f);  // 10000^(-j/64)
          float ang = (float)p * invf;
          ang -= 6.283185307179586f * floorf(ang * 0.15915494309189535f);
          float sv, cv;
          __sincosf(ang, &sv, &cv);
          float o0 = x0 * cv - x1 * sv, o1 = x1 * cv + x0 * sv;
          if constexpr (MODE == 0) { o0 *= CSC; o1 *= CSC; }
          __half* dst = (MODE == 0) ? g_Qh : g_Kh;
          dst[base + j]      = __float2half(o0);
          dst[base + j + 64] = __float2half(o1);
        }
  }
}

// ---------------- flash attention: out = softmax(Q K^T) V ----------------
// grid (2, 64): x = q-tile of 128 rows, y = (t*NH+h). 8 warps x 16 q-rows.
static constexpr int FPAD = 136;                          // padded row (halves), 16B-aligned
static constexpr int FLASH_SMEM = 5 * 128 * FPAD * 2;     // Q + 2xK + 2xV = 174080 B

__global__ void __launch_bounds__(256, 1) k_flash(float* __restrict__ out) {
  extern __shared__ __half fsm[];
  __half* Qs = fsm;                      // [128][FPAD]
  __half* Ks = fsm + 128 * FPAD;         // [2][128][FPAD]
  __half* Vs = fsm + 3 * 128 * FPAD;     // [2][128][FPAD]

  const int bz = blockIdx.y;
  const int q0 = blockIdx.x * 128;
  const int tid = threadIdx.x, lane = tid & 31, warp = tid >> 5;
  const int r0w = warp * 16;
  const __half* Qg = g_Qh + ((size_t)bz * SQ + q0) * HD;
  const __half* Kg = g_Kh + (size_t)bz * LK * HD;
  const __half* Vg = g_VhT + (size_t)bz * HD * LK;

  auto load_kv = [&](int j, int s) {
    const __half* kg = Kg + (size_t)j * 128 * HD;
#pragma unroll
    for (int i = 0; i < 8; i++) {
      int idx = tid + i * 256; int r = idx >> 4, c = (idx & 15) * 8;
      cp16(Ks + (size_t)s * 128 * FPAD + r * FPAD + c, kg + (size_t)r * HD + c);
    }
#pragma unroll
    for (int i = 0; i < 8; i++) {
      int idx = tid + i * 256; int r = idx >> 4, c = (idx & 15) * 8;
      cp16(Vs + (size_t)s * 128 * FPAD + r * FPAD + c, Vg + (size_t)r * LK + j * 128 + c);
    }
    cp_commit();
  };

  // Q + chunk0 in group 0, chunk1 in group 1
#pragma unroll
  for (int i = 0; i < 8; i++) {
    int idx = tid + i * 256; int r = idx >> 4, c = (idx & 15) * 8;
    cp16(Qs + r * FPAD + c, Qg + (size_t)r * HD + c);
  }
  load_kv(0, 0);
  load_kv(1, 1);

  float o[16][4];
#pragma unroll
  for (int f = 0; f < 16; f++)
#pragma unroll
    for (int e = 0; e < 4; e++) o[f][e] = 0.f;
  float mlo = -1e30f, mhi = -1e30f, llo = 0.f, lhi = 0.f;

  for (int j = 0; j < 32; j++) {
    if (j + 1 < 32) cp_wait<1>(); else cp_wait<0>();
    __syncthreads();
    const int s = j & 1;
    const __half* KsS = Ks + (size_t)s * 128 * FPAD;
    const __half* VsS = Vs + (size_t)s * 128 * FPAD;

    // S = Q K^T (already in log2 domain via Q pre-scale)
    float sfr[16][4];
#pragma unroll
    for (int f = 0; f < 16; f++)
#pragma unroll
      for (int e = 0; e < 4; e++) sfr[f][e] = 0.f;
#pragma unroll
    for (int ks = 0; ks < 8; ks++) {
      unsigned a[4];
      ldsm4(a, Qs + (r0w + ((lane >> 3) & 1) * 8 + (lane & 7)) * FPAD + ks * 16 + (lane >> 4) * 8);
#pragma unroll
      for (int f = 0; f < 8; f++) {
        unsigned b[4];
        ldsm4(b, KsS + (f * 16 + (lane >> 4) * 8 + (lane & 7)) * FPAD + ks * 16 + ((lane >> 3) & 1) * 8);
        mma16816(sfr[2 * f], a, b);
        mma16816(sfr[2 * f + 1], a, b + 2);
      }
    }

    // online softmax (base-2 domain); P emitted as packed fp16 A-fragments
    float cmlo = -1e30f, cmhi = -1e30f;
#pragma unroll
    for (int f = 0; f < 16; f++) {
      cmlo = fmaxf(cmlo, fmaxf(sfr[f][0], sfr[f][1]));
      cmhi = fmaxf(cmhi, fmaxf(sfr[f][2], sfr[f][3]));
    }
#pragma unroll
    for (int ofs = 1; ofs < 4; ofs <<= 1) {
      cmlo = fmaxf(cmlo, __shfl_xor_sync(0xffffffffu, cmlo, ofs));
      cmhi = fmaxf(cmhi, __shfl_xor_sync(0xffffffffu, cmhi, ofs));
    }
    float mnlo = fmaxf(mlo, cmlo), mnhi = fmaxf(mhi, cmhi);
    float alo = ex2f(mlo - mnlo), ahi = ex2f(mhi - mnhi);
    mlo = mnlo; mhi = mnhi;

    unsigned pa[8][4];
    float slo = 0.f, shi = 0.f;
#pragma unroll
    for (int f = 0; f < 16; f++) {
      __half2 dlo = __floats2half2_rn(sfr[f][0] - mnlo, sfr[f][1] - mnlo);
      __half2 dhi = __floats2half2_rn(sfr[f][2] - mnhi, sfr[f][3] - mnhi);
      unsigned plo = h2ex2(*(unsigned*)&dlo);
      unsigned phi = h2ex2(*(unsigned*)&dhi);
      int ks = f >> 1, half_ = (f & 1) * 2;
      pa[ks][half_ + 0] = plo;
      pa[ks][half_ + 1] = phi;
      float2 flo = __half22float2(*(__half2*)&plo);
      float2 fhi = __half22float2(*(__half2*)&phi);
      slo += flo.x + flo.y;
      shi += fhi.x + fhi.y;
    }
#pragma unroll
    for (int ofs = 1; ofs < 4; ofs <<= 1) {
      slo += __shfl_xor_sync(0xffffffffu, slo, ofs);
      shi += __shfl_xor_sync(0xffffffffu, shi, ofs);
    }
    llo = llo * alo + slo;
    lhi = lhi * ahi + shi;
#pragma unroll
    for (int f = 0; f < 16; f++) {
      o[f][0] *= alo; o[f][1] *= alo;
      o[f][2] *= ahi; o[f][3] *= ahi;
    }

    // O += P V
#pragma unroll
    for (int ks = 0; ks < 8; ks++) {
#pragma unroll
      for (int f = 0; f < 8; f++) {
        unsigned b[4];
        ldsm4(b, VsS + (f * 16 + (lane >> 4) * 8 + (lane & 7)) * FPAD + ks * 16 + ((lane >> 3) & 1) * 8);
        mma16816(o[2 * f], pa[ks], b);
        mma16816(o[2 * f + 1], pa[ks], b + 2);
      }
    }
    __syncthreads();
    if (j + 2 < 32) load_kv(j + 2, s);
  }

  // epilogue: normalize, write d_out[(t*SQ+s)*DM + h*HD + d]
  float ilo = 1.0f / llo, ihi = 1.0f / lhi;
  int t = bz >> 3, h = bz & 7;
  size_t rowbase = ((size_t)t * SQ + q0 + r0w + (lane >> 2)) * DM + (size_t)h * HD;
#pragma unroll
  for (int f = 0; f < 16; f++) {
    int c = f * 8 + (lane & 3) * 2;
    *(float2*)&out[rowbase + c] = make_float2(o[f][0] * ilo, o[f][1] * ilo);
    *(float2*)&out[rowbase + 8 * DM + c] = make_float2(o[f][2] * ihi, o[f][3] * ihi);
  }
}

// ---------------- input cast fp32 -> fp16 (dst via sel_ptr, device-resolved) ----------------
template<int DSEL>
__global__ void k_cast(const float* __restrict__ s) {
  __half* __restrict__ d = sel_ptr<DSEL>();
  size_t i = ((size_t)blockIdx.x * blockDim.x + threadIdx.x) * 8;
  float4 f0 = *(const float4*)(s + i);
  float4 f1 = *(const float4*)(s + i + 4);
  __half2 h[4];
  h[0] = __floats2half2_rn(f0.x, f0.y);
  h[1] = __floats2half2_rn(f0.z, f0.w);
  h[2] = __floats2half2_rn(f1.x, f1.y);
  h[3] = __floats2half2_rn(f1.z, f1.w);
  *(int4*)(d + i) = *(const int4*)h;
}

// ---------------- weight transpose+cast ----------------
__global__ void k_prep_w(const float* __restrict__ Wq, const float* __restrict__ Wk,
                         const float* __restrict__ Wv) {
  int i = blockIdx.x * blockDim.x + threadIdx.x;
  if (i >= DM * DM) return;
  int o = i / DM, in = i % DM;
  int src = in * DM + o;
  g_Wt[0][i] = __float2half(Wq[src]);
  g_Wt[1][i] = __float2half(Wk[src]);
  g_Wt[2][i] = __float2half(Wv[src]);
}

// ---------------- launch ----------------
extern "C" void kernel_launch(void* const* d_in, const int* in_sizes, int n_in,
                              void* d_out, int out_size) {
  const float* q  = (const float*)d_in[0];
  const float* k  = (const float*)d_in[1];
  const float* v  = (const float*)d_in[2];
  const float* Wq = (const float*)d_in[3];
  const float* bq = (const float*)d_in[4];
  const float* Wk = (const float*)d_in[5];
  const float* bk = (const float*)d_in[6];
  const float* Wv = (const float*)d_in[7];
  const float* bv = (const float*)d_in[8];
  float* out = (float*)d_out;
  (void)in_sizes; (void)n_in; (void)out_size;

  cudaFuncSetAttribute(k_flash, cudaFuncAttributeMaxDynamicSharedMemorySize, FLASH_SMEM);

  k_cast<3><<<(NQ * DM) / 2048, 256>>>(q);
  k_cast<4><<<(NK * DM) / 2048, 256>>>(k);
  k_cast<5><<<(NK * DM) / 2048, 256>>>(v);
  k_prep_w<<<(DM * DM + 255) / 256, 256>>>(Wq, Wk, Wv);

  // projections with fused bias + rope + layout epilogues
  k_gemm3<0, 3, 0><<<dim3(NH, NQ / 128), 256>>>(bq);
  k_gemm3<1, 4, 1><<<dim3(NH, NK / 128), 256>>>(bk);
  k_gemm3<2, 5, 2><<<dim3(NH, NK / 128), 256>>>(bv);

  // fused attention
  k_flash<<<dim3(2, 64), 256, FLASH_SMEM>>>(out);
}

// round 9
// speedup vs baseline: 1.9393x; 1.0704x over previous
#include <cuda_runtime.h>
#include <cuda_fp16.h>
#include <math.h>

static constexpr int DM = 1024, NH = 8, HD = 128;
static constexpr int TQ = 8, SQ = 256, TK = 32, SK = 1024;
static constexpr int NQ = TQ * SQ;         // 2048
static constexpr int NK = TK * SK;         // 32768
static constexpr int LK = (TK / TQ) * SK;  // 4096

// ---------------- static scratch ----------------
__device__ __half g_Wt[3][DM * DM];          // W^T fp16, [out][in]
__device__ __half g_Aq[(size_t)NQ * DM];     // fp16 inputs (cp.async-able)
__device__ __half g_Ak[(size_t)NK * DM];
__device__ __half g_Av[(size_t)NK * DM];
__device__ __half g_Qh[(size_t)NQ * DM];     // [t][h][s][d], pre-scaled by 1/sqrt(128)*log2e
__device__ __half g_Kh[(size_t)NK * DM];     // [tg][h][l][d]
__device__ __half g_VhT[(size_t)NK * DM];    // [tg][h][d][l]

__constant__ int c_tmap[8] = {0, 4, 8, 13, 17, 22, 26, 31};

template<int S> __device__ __forceinline__ __half* sel_ptr() {
  if constexpr (S == 0) return g_Wt[0];
  else if constexpr (S == 1) return g_Wt[1];
  else if constexpr (S == 2) return g_Wt[2];
  else if constexpr (S == 3) return g_Aq;
  else if constexpr (S == 4) return g_Ak;
  else if constexpr (S == 5) return g_Av;
  else if constexpr (S == 6) return g_Qh;
  else if constexpr (S == 7) return g_Kh;
  else return g_VhT;
}

// ---------------- primitives ----------------
__device__ __forceinline__ void mma16816(float d[4], const unsigned a[4], const unsigned b[2]) {
  asm volatile(
      "mma.sync.aligned.m16n8k16.row.col.f32.f16.f16.f32 "
      "{%0,%1,%2,%3},{%4,%5,%6,%7},{%8,%9},{%0,%1,%2,%3};\n"
      : "+f"(d[0]), "+f"(d[1]), "+f"(d[2]), "+f"(d[3])
      : "r"(a[0]), "r"(a[1]), "r"(a[2]), "r"(a[3]), "r"(b[0]), "r"(b[1]));
}
__device__ __forceinline__ void cp16(void* smem_dst, const void* gmem_src) {
  unsigned d = (unsigned)__cvta_generic_to_shared(smem_dst);
  asm volatile("cp.async.cg.shared.global [%0], [%1], 16;\n" :: "r"(d), "l"(gmem_src));
}
__device__ __forceinline__ void cp_commit() { asm volatile("cp.async.commit_group;\n"); }
template<int N> __device__ __forceinline__ void cp_wait() {
  asm volatile("cp.async.wait_group %0;\n" :: "n"(N));
}
__device__ __forceinline__ void ldsm4(unsigned r[4], const __half* p) {
  unsigned a = (unsigned)__cvta_generic_to_shared(p);
  asm volatile("ldmatrix.sync.aligned.m8n8.x4.shared.b16 {%0,%1,%2,%3},[%4];\n"
               : "=r"(r[0]), "=r"(r[1]), "=r"(r[2]), "=r"(r[3]) : "r"(a));
}
__device__ __forceinline__ float ex2f(float x) {
  float y; asm("ex2.approx.ftz.f32 %0, %1;" : "=f"(y) : "f"(x)); return y;
}
__device__ __forceinline__ unsigned h2ex2(unsigned x) {
  unsigned y; asm("ex2.approx.f16x2 %0, %1;" : "=r"(y) : "r"(x)); return y;
}

// ---------------- projection GEMM + fused bias/rope/layout epilogue ----------------
// C(MxN) = A(MxK,row) * B(NxK)^T ; blockIdx.x = head, blockIdx.y = m-tile
// A ldsm lane map: {r0-7 k0-7, r8-15 k0-7, r0-7 k8-15, r8-15 k8-15}  (A-order)
// B ldsm lane map (flash-proven, TRANSPOSED lane roles):
//   {n0-7 k0-7, n0-7 k8-15, n8-15 k0-7, n8-15 k8-15}  -> pairs (b, b+2)
// MODE 0 = Q (rope + softmax prescale), 1 = K (rope), 2 = V (transposed)
template<int MODE, int ASEL, int BSEL>
__global__ void __launch_bounds__(256, 2) k_gemm3(const float* __restrict__ bias) {
  constexpr int BM = 128, BN = 128, BK = 32, KD = DM;
  __shared__ __half As[2][BM][BK + 8];
  __shared__ __half Bs[2][BN][BK + 8];

  const __half* Ap = sel_ptr<ASEL>();
  const __half* Bp = sel_ptr<BSEL>();
  const size_t bm = (size_t)blockIdx.y * BM;
  const int h = blockIdx.x;
  const size_t bn = (size_t)h * BN;
  const int tid = threadIdx.x, lane = tid & 31, warp = tid >> 5;
  const int wm = warp & 1, wn = warp >> 1;  // 2x4 warps, 64x32 tiles
  const int NIT = KD / BK;

  auto load_stage = [&](int it, int s) {
    const int k0 = it * BK;
#pragma unroll
    for (int i = 0; i < 2; i++) {
      int idx = tid + i * 256; int r = idx >> 2, c = (idx & 3) * 8;
      cp16(&As[s][r][c], Ap + (bm + r) * KD + k0 + c);
    }
#pragma unroll
    for (int i = 0; i < 2; i++) {
      int idx = tid + i * 256; int r = idx >> 2, c = (idx & 3) * 8;
      cp16(&Bs[s][r][c], Bp + (bn + r) * KD + k0 + c);
    }
    cp_commit();
  };

  float acc[4][4][4];
#pragma unroll
  for (int mi = 0; mi < 4; mi++)
#pragma unroll
    for (int ni = 0; ni < 4; ni++)
#pragma unroll
      for (int e = 0; e < 4; e++) acc[mi][ni][e] = 0.f;

  load_stage(0, 0);
  load_stage(1, 1);

  // A-style lane mapping (rows split by lane>>3 bit, k-half by lane>>4)
  const int arow = ((lane >> 3) & 1) * 8 + (lane & 7);
  const int acol = (lane >> 4) * 8;
  // B-style lane mapping (k-half by (lane>>3)&1, n split by lane>>4) — flash-proven
  const int brow = (lane >> 4) * 8 + (lane & 7);
  const int bcol = ((lane >> 3) & 1) * 8;

  for (int it = 0; it < NIT; ++it) {
    if (it + 1 < NIT) cp_wait<1>(); else cp_wait<0>();
    __syncthreads();
    const int s = it & 1;
#pragma unroll
    for (int kk = 0; kk < BK; kk += 16) {
      unsigned a[4][4], bq[2][4];
#pragma unroll
      for (int mi = 0; mi < 4; mi++)
        ldsm4(a[mi], &As[s][wm * 64 + mi * 16 + arow][kk + acol]);
#pragma unroll
      for (int q = 0; q < 2; q++)
        ldsm4(bq[q], &Bs[s][q * 64 + wn * 16 + brow][kk + bcol]);
#pragma unroll
      for (int mi = 0; mi < 4; mi++) {
        mma16816(acc[mi][0], a[mi], &bq[0][0]);
        mma16816(acc[mi][1], a[mi], &bq[0][2]);
        mma16816(acc[mi][2], a[mi], &bq[1][0]);
        mma16816(acc[mi][3], a[mi], &bq[1][2]);
      }
    }
    __syncthreads();
    if (it + 2 < NIT) load_stage(it + 2, s);
  }

  if constexpr (MODE == 2) {
    // V: bias + cast + direct transpose to [z][d][l]
#pragma unroll
    for (int mi = 0; mi < 4; mi++)
#pragma unroll
      for (int ni = 0; ni < 4; ni++)
#pragma unroll
        for (int e = 0; e < 4; e++) {
          int token = (int)bm + wm * 64 + mi * 16 + (lane >> 2) + (e >> 1) * 8;
          int d = (ni >> 1) * 64 + wn * 16 + (ni & 1) * 8 + (lane & 3) * 2 + (e & 1);
          float val = acc[mi][ni][e] + bias[h * HD + d];
          int tg = token >> 12, l = token & 4095;
          g_VhT[((size_t)(tg * NH + h) * HD + d) * LK + l] = __float2half(val);
        }
  } else {
    constexpr float CSC = 0.08838834764831845f * 1.4426950408889634f;  // 1/sqrt(128)*log2e
#pragma unroll
    for (int mi = 0; mi < 4; mi++)
#pragma unroll
      for (int ni = 0; ni < 2; ni++)
#pragma unroll
        for (int e = 0; e < 4; e++) {
          int token = (int)bm + wm * 64 + mi * 16 + (lane >> 2) + (e >> 1) * 8;
          int j = wn * 16 + ni * 8 + (lane & 3) * 2 + (e & 1);
          float x0 = acc[mi][ni][e] + bias[h * HD + j];
          float x1 = acc[mi][ni + 2][e] + bias[h * HD + j + 64];
          int p; size_t base;
          if constexpr (MODE == 0) {
            int t = token >> 8, rem = token & 255;
            p = (j < 16) ? c_tmap[t] : (j < 40) ? 2 * (rem >> 4) + 1 : 2 * (rem & 15) + 1;
            base = ((size_t)(t * NH + h) * SQ + rem) * HD;
          } else {
            p = (j < 16) ? (token >> 10) : (j < 40) ? ((token >> 5) & 31) : (token & 31);
            base = ((size_t)((token >> 12) * NH + h) * LK + (token & 4095)) * HD;
          }
          float invf = ex2f(-(float)j * 0.20762050593046015f);  // 10000^(-j/64)
          float ang = (float)p * invf;
          ang -= 6.283185307179586f * floorf(ang * 0.15915494309189535f);
          float sv, cv;
          __sincosf(ang, &sv, &cv);
          float o0 = x0 * cv - x1 * sv, o1 = x1 * cv + x0 * sv;
          if constexpr (MODE == 0) { o0 *= CSC; o1 *= CSC; }
          __half* dst = (MODE == 0) ? g_Qh : g_Kh;
          dst[base + j]      = __float2half(o0);
          dst[base + j + 64] = __float2half(o1);
        }
  }
}

// ---------------- flash attention (unchanged, passing since round 6) ----------------
static constexpr int FPAD = 136;
static constexpr int FLASH_SMEM = 5 * 128 * FPAD * 2;

__global__ void __launch_bounds__(256, 1) k_flash(float* __restrict__ out) {
  extern __shared__ __half fsm[];
  __half* Qs = fsm;
  __half* Ks = fsm + 128 * FPAD;
  __half* Vs = fsm + 3 * 128 * FPAD;

  const int bz = blockIdx.y;
  const int q0 = blockIdx.x * 128;
  const int tid = threadIdx.x, lane = tid & 31, warp = tid >> 5;
  const int r0w = warp * 16;
  const __half* Qg = g_Qh + ((size_t)bz * SQ + q0) * HD;
  const __half* Kg = g_Kh + (size_t)bz * LK * HD;
  const __half* Vg = g_VhT + (size_t)bz * HD * LK;

  auto load_kv = [&](int j, int s) {
    const __half* kg = Kg + (size_t)j * 128 * HD;
#pragma unroll
    for (int i = 0; i < 8; i++) {
      int idx = tid + i * 256; int r = idx >> 4, c = (idx & 15) * 8;
      cp16(Ks + (size_t)s * 128 * FPAD + r * FPAD + c, kg + (size_t)r * HD + c);
    }
#pragma unroll
    for (int i = 0; i < 8; i++) {
      int idx = tid + i * 256; int r = idx >> 4, c = (idx & 15) * 8;
      cp16(Vs + (size_t)s * 128 * FPAD + r * FPAD + c, Vg + (size_t)r * LK + j * 128 + c);
    }
    cp_commit();
  };

#pragma unroll
  for (int i = 0; i < 8; i++) {
    int idx = tid + i * 256; int r = idx >> 4, c = (idx & 15) * 8;
    cp16(Qs + r * FPAD + c, Qg + (size_t)r * HD + c);
  }
  load_kv(0, 0);
  load_kv(1, 1);

  float o[16][4];
#pragma unroll
  for (int f = 0; f < 16; f++)
#pragma unroll
    for (int e = 0; e < 4; e++) o[f][e] = 0.f;
  float mlo = -1e30f, mhi = -1e30f, llo = 0.f, lhi = 0.f;

  for (int j = 0; j < 32; j++) {
    if (j + 1 < 32) cp_wait<1>(); else cp_wait<0>();
    __syncthreads();
    const int s = j & 1;
    const __half* KsS = Ks + (size_t)s * 128 * FPAD;
    const __half* VsS = Vs + (size_t)s * 128 * FPAD;

    float sfr[16][4];
#pragma unroll
    for (int f = 0; f < 16; f++)
#pragma unroll
      for (int e = 0; e < 4; e++) sfr[f][e] = 0.f;
#pragma unroll
    for (int ks = 0; ks < 8; ks++) {
      unsigned a[4];
      ldsm4(a, Qs + (r0w + ((lane >> 3) & 1) * 8 + (lane & 7)) * FPAD + ks * 16 + (lane >> 4) * 8);
#pragma unroll
      for (int f = 0; f < 8; f++) {
        unsigned b[4];
        ldsm4(b, KsS + (f * 16 + (lane >> 4) * 8 + (lane & 7)) * FPAD + ks * 16 + ((lane >> 3) & 1) * 8);
        mma16816(sfr[2 * f], a, b);
        mma16816(sfr[2 * f + 1], a, b + 2);
      }
    }

    float cmlo = -1e30f, cmhi = -1e30f;
#pragma unroll
    for (int f = 0; f < 16; f++) {
      cmlo = fmaxf(cmlo, fmaxf(sfr[f][0], sfr[f][1]));
      cmhi = fmaxf(cmhi, fmaxf(sfr[f][2], sfr[f][3]));
    }
#pragma unroll
    for (int ofs = 1; ofs < 4; ofs <<= 1) {
      cmlo = fmaxf(cmlo, __shfl_xor_sync(0xffffffffu, cmlo, ofs));
      cmhi = fmaxf(cmhi, __shfl_xor_sync(0xffffffffu, cmhi, ofs));
    }
    float mnlo = fmaxf(mlo, cmlo), mnhi = fmaxf(mhi, cmhi);
    float alo = ex2f(mlo - mnlo), ahi = ex2f(mhi - mnhi);
    mlo = mnlo; mhi = mnhi;

    unsigned pa[8][4];
    float slo = 0.f, shi = 0.f;
#pragma unroll
    for (int f = 0; f < 16; f++) {
      __half2 dlo = __floats2half2_rn(sfr[f][0] - mnlo, sfr[f][1] - mnlo);
      __half2 dhi = __floats2half2_rn(sfr[f][2] - mnhi, sfr[f][3] - mnhi);
      unsigned plo = h2ex2(*(unsigned*)&dlo);
      unsigned phi = h2ex2(*(unsigned*)&dhi);
      int ks = f >> 1, half_ = (f & 1) * 2;
      pa[ks][half_ + 0] = plo;
      pa[ks][half_ + 1] = phi;
      float2 flo = __half22float2(*(__half2*)&plo);
      float2 fhi = __half22float2(*(__half2*)&phi);
      slo += flo.x + flo.y;
      shi += fhi.x + fhi.y;
    }
#pragma unroll
    for (int ofs = 1; ofs < 4; ofs <<= 1) {
      slo += __shfl_xor_sync(0xffffffffu, slo, ofs);
      shi += __shfl_xor_sync(0xffffffffu, shi, ofs);
    }
    llo = llo * alo + slo;
    lhi = lhi * ahi + shi;
#pragma unroll
    for (int f = 0; f < 16; f++) {
      o[f][0] *= alo; o[f][1] *= alo;
      o[f][2] *= ahi; o[f][3] *= ahi;
    }

#pragma unroll
    for (int ks = 0; ks < 8; ks++) {
#pragma unroll
      for (int f = 0; f < 8; f++) {
        unsigned b[4];
        ldsm4(b, VsS + (f * 16 + (lane >> 4) * 8 + (lane & 7)) * FPAD + ks * 16 + ((lane >> 3) & 1) * 8);
        mma16816(o[2 * f], pa[ks], b);
        mma16816(o[2 * f + 1], pa[ks], b + 2);
      }
    }
    __syncthreads();
    if (j + 2 < 32) load_kv(j + 2, s);
  }

  float ilo = 1.0f / llo, ihi = 1.0f / lhi;
  int t = bz >> 3, h = bz & 7;
  size_t rowbase = ((size_t)t * SQ + q0 + r0w + (lane >> 2)) * DM + (size_t)h * HD;
#pragma unroll
  for (int f = 0; f < 16; f++) {
    int c = f * 8 + (lane & 3) * 2;
    *(float2*)&out[rowbase + c] = make_float2(o[f][0] * ilo, o[f][1] * ilo);
    *(float2*)&out[rowbase + 8 * DM + c] = make_float2(o[f][2] * ihi, o[f][3] * ihi);
  }
}

// ---------------- input cast fp32 -> fp16 (dst via sel_ptr, device-resolved) ----------------
template<int DSEL>
__global__ void k_cast(const float* __restrict__ s) {
  __half* __restrict__ d = sel_ptr<DSEL>();
  size_t i = ((size_t)blockIdx.x * blockDim.x + threadIdx.x) * 8;
  float4 f0 = *(const float4*)(s + i);
  float4 f1 = *(const float4*)(s + i + 4);
  __half2 h[4];
  h[0] = __floats2half2_rn(f0.x, f0.y);
  h[1] = __floats2half2_rn(f0.z, f0.w);
  h[2] = __floats2half2_rn(f1.x, f1.y);
  h[3] = __floats2half2_rn(f1.z, f1.w);
  *(int4*)(d + i) = *(const int4*)h;
}

// ---------------- weight transpose+cast (smem-tiled) ----------------
__global__ void k_prep_w(const float* __restrict__ Wq, const float* __restrict__ Wk,
                         const float* __restrict__ Wv) {
  __shared__ float ts[3][32][33];
  const int bo = blockIdx.x * 32;  // output-dim tile
  const int bi = blockIdx.y * 32;  // input-dim tile
  const int tx = threadIdx.x, ty = threadIdx.y;  // (32, 8)
#pragma unroll
  for (int i = 0; i < 32; i += 8) {
    int src = (bi + ty + i) * DM + bo + tx;  // W[in][o], coalesced in o
    ts[0][ty + i][tx] = Wq[src];
    ts[1][ty + i][tx] = Wk[src];
    ts[2][ty + i][tx] = Wv[src];
  }
  __syncthreads();
#pragma unroll
  for (int i = 0; i < 32; i += 8) {
    int dst = (bo + ty + i) * DM + bi + tx;  // Wt[o][in], coalesced in in
    g_Wt[0][dst] = __float2half(ts[0][tx][ty + i]);
    g_Wt[1][dst] = __float2half(ts[1][tx][ty + i]);
    g_Wt[2][dst] = __float2half(ts[2][tx][ty + i]);
  }
}

// ---------------- launch ----------------
extern "C" void kernel_launch(void* const* d_in, const int* in_sizes, int n_in,
                              void* d_out, int out_size) {
  const float* q  = (const float*)d_in[0];
  const float* k  = (const float*)d_in[1];
  const float* v  = (const float*)d_in[2];
  const float* Wq = (const float*)d_in[3];
  const float* bq = (const float*)d_in[4];
  const float* Wk = (const float*)d_in[5];
  const float* bk = (const float*)d_in[6];
  const float* Wv = (const float*)d_in[7];
  const float* bv = (const float*)d_in[8];
  float* out = (float*)d_out;
  (void)in_sizes; (void)n_in; (void)out_size;

  cudaFuncSetAttribute(k_flash, cudaFuncAttributeMaxDynamicSharedMemorySize, FLASH_SMEM);

  k_cast<3><<<(NQ * DM) / 2048, 256>>>(q);
  k_cast<4><<<(NK * DM) / 2048, 256>>>(k);
  k_cast<5><<<(NK * DM) / 2048, 256>>>(v);
  k_prep_w<<<dim3(32, 32), dim3(32, 8)>>>(Wq, Wk, Wv);

  // projections with fused bias + rope + layout epilogues
  k_gemm3<0, 3, 0><<<dim3(NH, NQ / 128), 256>>>(bq);
  k_gemm3<1, 4, 1><<<dim3(NH, NK / 128), 256>>>(bk);
  k_gemm3<2, 5, 2><<<dim3(NH, NK / 128), 256>>>(bv);

  // fused attention
  k_flash<<<dim3(2, 64), 256, FLASH_SMEM>>>(out);
}

// round 10
// speedup vs baseline: 2.1615x; 1.1146x over previous
#include <cuda_runtime.h>
#include <cuda_fp16.h>
#include <math.h>

static constexpr int DM = 1024, NH = 8, HD = 128;
static constexpr int TQ = 8, SQ = 256, TK = 32, SK = 1024;
static constexpr int NQ = TQ * SQ;         // 2048
static constexpr int NK = TK * SK;         // 32768
static constexpr int LK = (TK / TQ) * SK;  // 4096

// ---------------- static scratch ----------------
__device__ __half g_Wt[3][DM * DM];          // W^T fp16, [out][in]
__device__ __half g_Aq[(size_t)NQ * DM];     // fp16 inputs (cp.async-able)
__device__ __half g_Ak[(size_t)NK * DM];
__device__ __half g_Av[(size_t)NK * DM];
__device__ __half g_Qh[(size_t)NQ * DM];     // [t][h][s][d], pre-scaled by 1/sqrt(128)*log2e
__device__ __half g_Kh[(size_t)NK * DM];     // [tg][h][l][d]
__device__ __half g_VhT[(size_t)NK * DM];    // [tg][h][d][l]

__constant__ int c_tmap[8] = {0, 4, 8, 13, 17, 22, 26, 31};

template<int S> __device__ __forceinline__ __half* sel_ptr() {
  if constexpr (S == 0) return g_Wt[0];
  else if constexpr (S == 1) return g_Wt[1];
  else if constexpr (S == 2) return g_Wt[2];
  else if constexpr (S == 3) return g_Aq;
  else if constexpr (S == 4) return g_Ak;
  else if constexpr (S == 5) return g_Av;
  else if constexpr (S == 6) return g_Qh;
  else if constexpr (S == 7) return g_Kh;
  else return g_VhT;
}

// ---------------- primitives ----------------
__device__ __forceinline__ void mma16816(float d[4], const unsigned a[4], const unsigned b[2]) {
  asm volatile(
      "mma.sync.aligned.m16n8k16.row.col.f32.f16.f16.f32 "
      "{%0,%1,%2,%3},{%4,%5,%6,%7},{%8,%9},{%0,%1,%2,%3};\n"
      : "+f"(d[0]), "+f"(d[1]), "+f"(d[2]), "+f"(d[3])
      : "r"(a[0]), "r"(a[1]), "r"(a[2]), "r"(a[3]), "r"(b[0]), "r"(b[1]));
}
__device__ __forceinline__ void cp16(void* smem_dst, const void* gmem_src) {
  unsigned d = (unsigned)__cvta_generic_to_shared(smem_dst);
  asm volatile("cp.async.cg.shared.global [%0], [%1], 16;\n" :: "r"(d), "l"(gmem_src));
}
__device__ __forceinline__ void cp_commit() { asm volatile("cp.async.commit_group;\n"); }
template<int N> __device__ __forceinline__ void cp_wait() {
  asm volatile("cp.async.wait_group %0;\n" :: "n"(N));
}
__device__ __forceinline__ void ldsm4(unsigned r[4], const __half* p) {
  unsigned a = (unsigned)__cvta_generic_to_shared(p);
  asm volatile("ldmatrix.sync.aligned.m8n8.x4.shared.b16 {%0,%1,%2,%3},[%4];\n"
               : "=r"(r[0]), "=r"(r[1]), "=r"(r[2]), "=r"(r[3]) : "r"(a));
}
__device__ __forceinline__ float ex2f(float x) {
  float y; asm("ex2.approx.ftz.f32 %0, %1;" : "=f"(y) : "f"(x)); return y;
}
__device__ __forceinline__ unsigned h2ex2(unsigned x) {
  unsigned y; asm("ex2.approx.f16x2 %0, %1;" : "=r"(y) : "r"(x)); return y;
}

// ---------------- projection GEMM + fused bias/rope/layout epilogue ----------------
// C(MxN) = A(MxK,row) * B(NxK)^T ; blockIdx.x = head, blockIdx.y = m-tile
// 3-stage cp.async pipeline, BK=64, ONE barrier per iteration:
//   preload stages 0,1; at iter it: wait(group it) -> barrier -> issue load for
//   stage it+2 into buffer (it+2)%3 == (it-1)%3 (readers finished at it-1, proven
//   by the barrier) -> compute stage it%3.
// MODE 0 = Q (rope + softmax prescale), 1 = K (rope), 2 = V (transposed)
static constexpr int PBK = 64;                 // k-depth per stage
static constexpr int PROW = PBK + 8;           // padded row in halves (144 B)
static constexpr int POPH = 128 * PROW;        // one operand, halves (9216)
static constexpr int PSTG_H = 2 * POPH;        // stage size in halves (A+B)
static constexpr int PROJ_SMEM = 3 * PSTG_H * 2;  // bytes = 110592

template<int MODE, int ASEL, int BSEL>
__global__ void __launch_bounds__(256, 2) k_gemm3(const float* __restrict__ bias) {
  constexpr int BM = 128, KD = DM;
  extern __shared__ __half sm[];

  const __half* Ap = sel_ptr<ASEL>();
  const __half* Bp = sel_ptr<BSEL>();
  const size_t bm = (size_t)blockIdx.y * BM;
  const int h = blockIdx.x;
  const size_t bn = (size_t)h * 128;
  const int tid = threadIdx.x, lane = tid & 31, warp = tid >> 5;
  const int wm = warp & 1, wn = warp >> 1;  // 2x4 warps, 64x32 tiles
  constexpr int NIT = KD / PBK;             // 16

  auto load_stage = [&](int it, int s) {
    const int k0 = it * PBK;
    __half* As = sm + s * PSTG_H;
    __half* Bs = As + POPH;
#pragma unroll
    for (int i = 0; i < 4; i++) {  // A: 128 rows x 8 int4 = 1024
      int idx = tid + i * 256; int r = idx >> 3, c = (idx & 7) * 8;
      cp16(As + r * PROW + c, Ap + (bm + r) * KD + k0 + c);
    }
#pragma unroll
    for (int i = 0; i < 4; i++) {  // B: 128 rows x 8 int4 = 1024
      int idx = tid + i * 256; int r = idx >> 3, c = (idx & 7) * 8;
      cp16(Bs + r * PROW + c, Bp + (bn + r) * KD + k0 + c);
    }
    cp_commit();
  };

  float acc[4][4][4];
#pragma unroll
  for (int mi = 0; mi < 4; mi++)
#pragma unroll
    for (int ni = 0; ni < 4; ni++)
#pragma unroll
      for (int e = 0; e < 4; e++) acc[mi][ni][e] = 0.f;

  load_stage(0, 0);
  load_stage(1, 1);

  // A-style lane mapping (rows by (lane>>3)&1, k-half by lane>>4)
  const int arow = ((lane >> 3) & 1) * 8 + (lane & 7);
  const int acol = (lane >> 4) * 8;
  // B-style lane mapping (k-half by (lane>>3)&1, n-half by lane>>4) — flash-proven
  const int brow = (lane >> 4) * 8 + (lane & 7);
  const int bcol = ((lane >> 3) & 1) * 8;

  for (int it = 0; it < NIT; ++it) {
    if (it + 1 < NIT) cp_wait<1>(); else cp_wait<0>();
    __syncthreads();
    if (it + 3 <= NIT) load_stage(it + 2, (it + 2) % 3);
    const __half* As = sm + (it % 3) * PSTG_H;
    const __half* Bs = As + POPH;
#pragma unroll
    for (int kk = 0; kk < PBK; kk += 16) {
      unsigned a[4][4], bq[2][4];
#pragma unroll
      for (int mi = 0; mi < 4; mi++)
        ldsm4(a[mi], As + (wm * 64 + mi * 16 + arow) * PROW + kk + acol);
#pragma unroll
      for (int q = 0; q < 2; q++)
        ldsm4(bq[q], Bs + (q * 64 + wn * 16 + brow) * PROW + kk + bcol);
#pragma unroll
      for (int mi = 0; mi < 4; mi++) {
        mma16816(acc[mi][0], a[mi], &bq[0][0]);
        mma16816(acc[mi][1], a[mi], &bq[0][2]);
        mma16816(acc[mi][2], a[mi], &bq[1][0]);
        mma16816(acc[mi][3], a[mi], &bq[1][2]);
      }
    }
  }

  if constexpr (MODE == 2) {
    // V: bias + cast + direct transpose to [z][d][l]
#pragma unroll
    for (int mi = 0; mi < 4; mi++)
#pragma unroll
      for (int ni = 0; ni < 4; ni++)
#pragma unroll
        for (int e = 0; e < 4; e++) {
          int token = (int)bm + wm * 64 + mi * 16 + (lane >> 2) + (e >> 1) * 8;
          int d = (ni >> 1) * 64 + wn * 16 + (ni & 1) * 8 + (lane & 3) * 2 + (e & 1);
          float val = acc[mi][ni][e] + bias[h * HD + d];
          int tg = token >> 12, l = token & 4095;
          g_VhT[((size_t)(tg * NH + h) * HD + d) * LK + l] = __float2half(val);
        }
  } else {
    constexpr float CSC = 0.08838834764831845f * 1.4426950408889634f;  // 1/sqrt(128)*log2e
#pragma unroll
    for (int mi = 0; mi < 4; mi++)
#pragma unroll
      for (int ni = 0; ni < 2; ni++)
#pragma unroll
        for (int e = 0; e < 4; e++) {
          int token = (int)bm + wm * 64 + mi * 16 + (lane >> 2) + (e >> 1) * 8;
          int j = wn * 16 + ni * 8 + (lane & 3) * 2 + (e & 1);
          float x0 = acc[mi][ni][e] + bias[h * HD + j];
          float x1 = acc[mi][ni + 2][e] + bias[h * HD + j + 64];
          int p; size_t base;
          if constexpr (MODE == 0) {
            int t = token >> 8, rem = token & 255;
            p = (j < 16) ? c_tmap[t] : (j < 40) ? 2 * (rem >> 4) + 1 : 2 * (rem & 15) + 1;
            base = ((size_t)(t * NH + h) * SQ + rem) * HD;
          } else {
            p = (j < 16) ? (token >> 10) : (j < 40) ? ((token >> 5) & 31) : (token & 31);
            base = ((size_t)((token >> 12) * NH + h) * LK + (token & 4095)) * HD;
          }
          float invf = ex2f(-(float)j * 0.20762050593046015f);  // 10000^(-j/64)
          float ang = (float)p * invf;
          ang -= 6.283185307179586f * floorf(ang * 0.15915494309189535f);
          float sv, cv;
          __sincosf(ang, &sv, &cv);
          float o0 = x0 * cv - x1 * sv, o1 = x1 * cv + x0 * sv;
          if constexpr (MODE == 0) { o0 *= CSC; o1 *= CSC; }
          __half* dst = (MODE == 0) ? g_Qh : g_Kh;
          dst[base + j]      = __float2half(o0);
          dst[base + j + 64] = __float2half(o1);
        }
  }
}

// ---------------- flash attention (unchanged, passing since round 6) ----------------
static constexpr int FPAD = 136;
static constexpr int FLASH_SMEM = 5 * 128 * FPAD * 2;

__global__ void __launch_bounds__(256, 1) k_flash(float* __restrict__ out) {
  extern __shared__ __half fsm[];
  __half* Qs = fsm;
  __half* Ks = fsm + 128 * FPAD;
  __half* Vs = fsm + 3 * 128 * FPAD;

  const int bz = blockIdx.y;
  const int q0 = blockIdx.x * 128;
  const int tid = threadIdx.x, lane = tid & 31, warp = tid >> 5;
  const int r0w = warp * 16;
  const __half* Qg = g_Qh + ((size_t)bz * SQ + q0) * HD;
  const __half* Kg = g_Kh + (size_t)bz * LK * HD;
  const __half* Vg = g_VhT + (size_t)bz * HD * LK;

  auto load_kv = [&](int j, int s) {
    const __half* kg = Kg + (size_t)j * 128 * HD;
#pragma unroll
    for (int i = 0; i < 8; i++) {
      int idx = tid + i * 256; int r = idx >> 4, c = (idx & 15) * 8;
      cp16(Ks + (size_t)s * 128 * FPAD + r * FPAD + c, kg + (size_t)r * HD + c);
    }
#pragma unroll
    for (int i = 0; i < 8; i++) {
      int idx = tid + i * 256; int r = idx >> 4, c = (idx & 15) * 8;
      cp16(Vs + (size_t)s * 128 * FPAD + r * FPAD + c, Vg + (size_t)r * LK + j * 128 + c);
    }
    cp_commit();
  };

#pragma unroll
  for (int i = 0; i < 8; i++) {
    int idx = tid + i * 256; int r = idx >> 4, c = (idx & 15) * 8;
    cp16(Qs + r * FPAD + c, Qg + (size_t)r * HD + c);
  }
  load_kv(0, 0);
  load_kv(1, 1);

  float o[16][4];
#pragma unroll
  for (int f = 0; f < 16; f++)
#pragma unroll
    for (int e = 0; e < 4; e++) o[f][e] = 0.f;
  float mlo = -1e30f, mhi = -1e30f, llo = 0.f, lhi = 0.f;

  for (int j = 0; j < 32; j++) {
    if (j + 1 < 32) cp_wait<1>(); else cp_wait<0>();
    __syncthreads();
    const int s = j & 1;
    const __half* KsS = Ks + (size_t)s * 128 * FPAD;
    const __half* VsS = Vs + (size_t)s * 128 * FPAD;

    float sfr[16][4];
#pragma unroll
    for (int f = 0; f < 16; f++)
#pragma unroll
      for (int e = 0; e < 4; e++) sfr[f][e] = 0.f;
#pragma unroll
    for (int ks = 0; ks < 8; ks++) {
      unsigned a[4];
      ldsm4(a, Qs + (r0w + ((lane >> 3) & 1) * 8 + (lane & 7)) * FPAD + ks * 16 + (lane >> 4) * 8);
#pragma unroll
      for (int f = 0; f < 8; f++) {
        unsigned b[4];
        ldsm4(b, KsS + (f * 16 + (lane >> 4) * 8 + (lane & 7)) * FPAD + ks * 16 + ((lane >> 3) & 1) * 8);
        mma16816(sfr[2 * f], a, b);
        mma16816(sfr[2 * f + 1], a, b + 2);
      }
    }

    float cmlo = -1e30f, cmhi = -1e30f;
#pragma unroll
    for (int f = 0; f < 16; f++) {
      cmlo = fmaxf(cmlo, fmaxf(sfr[f][0], sfr[f][1]));
      cmhi = fmaxf(cmhi, fmaxf(sfr[f][2], sfr[f][3]));
    }
#pragma unroll
    for (int ofs = 1; ofs < 4; ofs <<= 1) {
      cmlo = fmaxf(cmlo, __shfl_xor_sync(0xffffffffu, cmlo, ofs));
      cmhi = fmaxf(cmhi, __shfl_xor_sync(0xffffffffu, cmhi, ofs));
    }
    float mnlo = fmaxf(mlo, cmlo), mnhi = fmaxf(mhi, cmhi);
    float alo = ex2f(mlo - mnlo), ahi = ex2f(mhi - mnhi);
    mlo = mnlo; mhi = mnhi;

    unsigned pa[8][4];
    float slo = 0.f, shi = 0.f;
#pragma unroll
    for (int f = 0; f < 16; f++) {
      __half2 dlo = __floats2half2_rn(sfr[f][0] - mnlo, sfr[f][1] - mnlo);
      __half2 dhi = __floats2half2_rn(sfr[f][2] - mnhi, sfr[f][3] - mnhi);
      unsigned plo = h2ex2(*(unsigned*)&dlo);
      unsigned phi = h2ex2(*(unsigned*)&dhi);
      int ks = f >> 1, half_ = (f & 1) * 2;
      pa[ks][half_ + 0] = plo;
      pa[ks][half_ + 1] = phi;
      float2 flo = __half22float2(*(__half2*)&plo);
      float2 fhi = __half22float2(*(__half2*)&phi);
      slo += flo.x + flo.y;
      shi += fhi.x + fhi.y;
    }
#pragma unroll
    for (int ofs = 1; ofs < 4; ofs <<= 1) {
      slo += __shfl_xor_sync(0xffffffffu, slo, ofs);
      shi += __shfl_xor_sync(0xffffffffu, shi, ofs);
    }
    llo = llo * alo + slo;
    lhi = lhi * ahi + shi;
#pragma unroll
    for (int f = 0; f < 16; f++) {
      o[f][0] *= alo; o[f][1] *= alo;
      o[f][2] *= ahi; o[f][3] *= ahi;
    }

#pragma unroll
    for (int ks = 0; ks < 8; ks++) {
#pragma unroll
      for (int f = 0; f < 8; f++) {
        unsigned b[4];
        ldsm4(b, VsS + (f * 16 + (lane >> 4) * 8 + (lane & 7)) * FPAD + ks * 16 + ((lane >> 3) & 1) * 8);
        mma16816(o[2 * f], pa[ks], b);
        mma16816(o[2 * f + 1], pa[ks], b + 2);
      }
    }
    __syncthreads();
    if (j + 2 < 32) load_kv(j + 2, s);
  }

  float ilo = 1.0f / llo, ihi = 1.0f / lhi;
  int t = bz >> 3, h = bz & 7;
  size_t rowbase = ((size_t)t * SQ + q0 + r0w + (lane >> 2)) * DM + (size_t)h * HD;
#pragma unroll
  for (int f = 0; f < 16; f++) {
    int c = f * 8 + (lane & 3) * 2;
    *(float2*)&out[rowbase + c] = make_float2(o[f][0] * ilo, o[f][1] * ilo);
    *(float2*)&out[rowbase + 8 * DM + c] = make_float2(o[f][2] * ihi, o[f][3] * ihi);
  }
}

// ---------------- input cast fp32 -> fp16 (dst via sel_ptr, device-resolved) ----------------
template<int DSEL>
__global__ void k_cast(const float* __restrict__ s) {
  __half* __restrict__ d = sel_ptr<DSEL>();
  size_t i = ((size_t)blockIdx.x * blockDim.x + threadIdx.x) * 8;
  float4 f0 = *(const float4*)(s + i);
  float4 f1 = *(const float4*)(s + i + 4);
  __half2 h[4];
  h[0] = __floats2half2_rn(f0.x, f0.y);
  h[1] = __floats2half2_rn(f0.z, f0.w);
  h[2] = __floats2half2_rn(f1.x, f1.y);
  h[3] = __floats2half2_rn(f1.z, f1.w);
  *(int4*)(d + i) = *(const int4*)h;
}

// ---------------- weight transpose+cast (smem-tiled) ----------------
__global__ void k_prep_w(const float* __restrict__ Wq, const float* __restrict__ Wk,
                         const float* __restrict__ Wv) {
  __shared__ float ts[3][32][33];
  const int bo = blockIdx.x * 32;
  const int bi = blockIdx.y * 32;
  const int tx = threadIdx.x, ty = threadIdx.y;  // (32, 8)
#pragma unroll
  for (int i = 0; i < 32; i += 8) {
    int src = (bi + ty + i) * DM + bo + tx;
    ts[0][ty + i][tx] = Wq[src];
    ts[1][ty + i][tx] = Wk[src];
    ts[2][ty + i][tx] = Wv[src];
  }
  __syncthreads();
#pragma unroll
  for (int i = 0; i < 32; i += 8) {
    int dst = (bo + ty + i) * DM + bi + tx;
    g_Wt[0][dst] = __float2half(ts[0][tx][ty + i]);
    g_Wt[1][dst] = __float2half(ts[1][tx][ty + i]);
    g_Wt[2][dst] = __float2half(ts[2][tx][ty + i]);
  }
}

// ---------------- launch ----------------
extern "C" void kernel_launch(void* const* d_in, const int* in_sizes, int n_in,
                              void* d_out, int out_size) {
  const float* q  = (const float*)d_in[0];
  const float* k  = (const float*)d_in[1];
  const float* v  = (const float*)d_in[2];
  const float* Wq = (const float*)d_in[3];
  const float* bq = (const float*)d_in[4];
  const float* Wk = (const float*)d_in[5];
  const float* bk = (const float*)d_in[6];
  const float* Wv = (const float*)d_in[7];
  const float* bv = (const float*)d_in[8];
  float* out = (float*)d_out;
  (void)in_sizes; (void)n_in; (void)out_size;

  cudaFuncSetAttribute(k_flash, cudaFuncAttributeMaxDynamicSharedMemorySize, FLASH_SMEM);
  cudaFuncSetAttribute(k_gemm3<0, 3, 0>, cudaFuncAttributeMaxDynamicSharedMemorySize, PROJ_SMEM);
  cudaFuncSetAttribute(k_gemm3<1, 4, 1>, cudaFuncAttributeMaxDynamicSharedMemorySize, PROJ_SMEM);
  cudaFuncSetAttribute(k_gemm3<2, 5, 2>, cudaFuncAttributeMaxDynamicSharedMemorySize, PROJ_SMEM);

  k_cast<3><<<(NQ * DM) / 2048, 256>>>(q);
  k_cast<4><<<(NK * DM) / 2048, 256>>>(k);
  k_cast<5><<<(NK * DM) / 2048, 256>>>(v);
  k_prep_w<<<dim3(32, 32), dim3(32, 8)>>>(Wq, Wk, Wv);

  // projections with fused bias + rope + layout epilogues
  k_gemm3<0, 3, 0><<<dim3(NH, NQ / 128), 256, PROJ_SMEM>>>(bq);
  k_gemm3<1, 4, 1><<<dim3(NH, NK / 128), 256, PROJ_SMEM>>>(bk);
  k_gemm3<2, 5, 2><<<dim3(NH, NK / 128), 256, PROJ_SMEM>>>(bv);

  // fused attention
  k_flash<<<dim3(2, 64), 256, FLASH_SMEM>>>(out);
}

// round 11
// speedup vs baseline: 2.3534x; 1.0887x over previous
#include <cuda_runtime.h>
#include <cuda_fp16.h>
#include <math.h>

static constexpr int DM = 1024, NH = 8, HD = 128;
static constexpr int TQ = 8, SQ = 256, TK = 32, SK = 1024;
static constexpr int NQ = TQ * SQ;         // 2048
static constexpr int NK = TK * SK;         // 32768
static constexpr int LK = (TK / TQ) * SK;  // 4096

// ---------------- static scratch ----------------
__device__ __half g_Wt[3][DM * DM];          // W^T fp16, [out][in]
__device__ __half g_Aq[(size_t)NQ * DM];     // fp16 inputs (cp.async-able)
__device__ __half g_Ak[(size_t)NK * DM];
__device__ __half g_Av[(size_t)NK * DM];
__device__ __half g_Qh[(size_t)NQ * DM];     // [t][h][s][d], pre-scaled by 1/sqrt(128)*log2e
__device__ __half g_Kh[(size_t)NK * DM];     // [tg][h][l][d]
__device__ __half g_VhT[(size_t)NK * DM];    // [tg][h][d][l]

__constant__ int c_tmap[8] = {0, 4, 8, 13, 17, 22, 26, 31};

template<int S> __device__ __forceinline__ __half* sel_ptr() {
  if constexpr (S == 0) return g_Wt[0];
  else if constexpr (S == 1) return g_Wt[1];
  else if constexpr (S == 2) return g_Wt[2];
  else if constexpr (S == 3) return g_Aq;
  else if constexpr (S == 4) return g_Ak;
  else if constexpr (S == 5) return g_Av;
  else if constexpr (S == 6) return g_Qh;
  else if constexpr (S == 7) return g_Kh;
  else return g_VhT;
}

// ---------------- primitives ----------------
__device__ __forceinline__ void mma16816(float d[4], const unsigned a[4], const unsigned b[2]) {
  asm volatile(
      "mma.sync.aligned.m16n8k16.row.col.f32.f16.f16.f32 "
      "{%0,%1,%2,%3},{%4,%5,%6,%7},{%8,%9},{%0,%1,%2,%3};\n"
      : "+f"(d[0]), "+f"(d[1]), "+f"(d[2]), "+f"(d[3])
      : "r"(a[0]), "r"(a[1]), "r"(a[2]), "r"(a[3]), "r"(b[0]), "r"(b[1]));
}
__device__ __forceinline__ void cp16(void* smem_dst, const void* gmem_src) {
  unsigned d = (unsigned)__cvta_generic_to_shared(smem_dst);
  asm volatile("cp.async.cg.shared.global [%0], [%1], 16;\n" :: "r"(d), "l"(gmem_src));
}
__device__ __forceinline__ void cp_commit() { asm volatile("cp.async.commit_group;\n"); }
template<int N> __device__ __forceinline__ void cp_wait() {
  asm volatile("cp.async.wait_group %0;\n" :: "n"(N));
}
__device__ __forceinline__ void ldsm4(unsigned r[4], const __half* p) {
  unsigned a = (unsigned)__cvta_generic_to_shared(p);
  asm volatile("ldmatrix.sync.aligned.m8n8.x4.shared.b16 {%0,%1,%2,%3},[%4];\n"
               : "=r"(r[0]), "=r"(r[1]), "=r"(r[2]), "=r"(r[3]) : "r"(a));
}
__device__ __forceinline__ float ex2f(float x) {
  float y; asm("ex2.approx.ftz.f32 %0, %1;" : "=f"(y) : "f"(x)); return y;
}
__device__ __forceinline__ unsigned h2ex2(unsigned x) {
  unsigned y; asm("ex2.approx.f16x2 %0, %1;" : "=r"(y) : "r"(x)); return y;
}

// ---------------- projection GEMM + fused bias/rope/layout epilogue ----------------
// Mainloop identical to round 10 (3-stage cp.async, BK=64, one barrier/iter).
// NEW: epilogue staged through smem -> all gmem writes are contiguous 256B rows
// (was: 2B scattered stores; V had ~16x sector amplification).
// MODE 0 = Q (rope + prescale), 1 = K (rope), 2 = V (transposed to [d][l])
static constexpr int PBK = 64;
static constexpr int PROW = PBK + 8;
static constexpr int POPH = 128 * PROW;
static constexpr int PSTG_H = 2 * POPH;
static constexpr int PROJ_SMEM = 3 * PSTG_H * 2;  // 110592 B (>= 128*136*2 epilogue tile)
static constexpr int EROW = 136;                  // epilogue smem row stride (halves)

template<int MODE, int ASEL, int BSEL>
__global__ void __launch_bounds__(256, 2) k_gemm3(const float* __restrict__ bias) {
  constexpr int BM = 128, KD = DM;
  extern __shared__ __half sm[];

  const __half* Ap = sel_ptr<ASEL>();
  const __half* Bp = sel_ptr<BSEL>();
  const size_t bm = (size_t)blockIdx.y * BM;
  const int h = blockIdx.x;
  const size_t bn = (size_t)h * 128;
  const int tid = threadIdx.x, lane = tid & 31, warp = tid >> 5;
  const int wm = warp & 1, wn = warp >> 1;  // 2x4 warps, 64x32 tiles
  constexpr int NIT = KD / PBK;             // 16

  auto load_stage = [&](int it, int s) {
    const int k0 = it * PBK;
    __half* As = sm + s * PSTG_H;
    __half* Bs = As + POPH;
#pragma unroll
    for (int i = 0; i < 4; i++) {
      int idx = tid + i * 256; int r = idx >> 3, c = (idx & 7) * 8;
      cp16(As + r * PROW + c, Ap + (bm + r) * KD + k0 + c);
    }
#pragma unroll
    for (int i = 0; i < 4; i++) {
      int idx = tid + i * 256; int r = idx >> 3, c = (idx & 7) * 8;
      cp16(Bs + r * PROW + c, Bp + (bn + r) * KD + k0 + c);
    }
    cp_commit();
  };

  float acc[4][4][4];
#pragma unroll
  for (int mi = 0; mi < 4; mi++)
#pragma unroll
    for (int ni = 0; ni < 4; ni++)
#pragma unroll
      for (int e = 0; e < 4; e++) acc[mi][ni][e] = 0.f;

  load_stage(0, 0);
  load_stage(1, 1);

  const int arow = ((lane >> 3) & 1) * 8 + (lane & 7);
  const int acol = (lane >> 4) * 8;
  const int brow = (lane >> 4) * 8 + (lane & 7);
  const int bcol = ((lane >> 3) & 1) * 8;

  for (int it = 0; it < NIT; ++it) {
    if (it + 1 < NIT) cp_wait<1>(); else cp_wait<0>();
    __syncthreads();
    if (it + 3 <= NIT) load_stage(it + 2, (it + 2) % 3);
    const __half* As = sm + (it % 3) * PSTG_H;
    const __half* Bs = As + POPH;
#pragma unroll
    for (int kk = 0; kk < PBK; kk += 16) {
      unsigned a[4][4], bq[2][4];
#pragma unroll
      for (int mi = 0; mi < 4; mi++)
        ldsm4(a[mi], As + (wm * 64 + mi * 16 + arow) * PROW + kk + acol);
#pragma unroll
      for (int q = 0; q < 2; q++)
        ldsm4(bq[q], Bs + (q * 64 + wn * 16 + brow) * PROW + kk + bcol);
#pragma unroll
      for (int mi = 0; mi < 4; mi++) {
        mma16816(acc[mi][0], a[mi], &bq[0][0]);
        mma16816(acc[mi][1], a[mi], &bq[0][2]);
        mma16816(acc[mi][2], a[mi], &bq[1][0]);
        mma16816(acc[mi][3], a[mi], &bq[1][2]);
      }
    }
  }

  // ---- epilogue: stage into smem, then coalesced 256B-row writes ----
  __syncthreads();  // all pipeline smem reads done; reuse sm as [128][EROW] tile
  __half* ep = sm;

  if constexpr (MODE == 2) {
    // transposed in smem: ep[d][tokenLocal]
#pragma unroll
    for (int mi = 0; mi < 4; mi++)
#pragma unroll
      for (int ni = 0; ni < 4; ni++)
#pragma unroll
        for (int e = 0; e < 4; e++) {
          int tl = wm * 64 + mi * 16 + (lane >> 2) + (e >> 1) * 8;
          int d = (ni >> 1) * 64 + wn * 16 + (ni & 1) * 8 + (lane & 3) * 2 + (e & 1);
          ep[d * EROW + tl] = __float2half(acc[mi][ni][e] + bias[h * HD + d]);
        }
  } else {
    constexpr float CSC = 0.08838834764831845f * 1.4426950408889634f;  // 1/sqrt(128)*log2e
#pragma unroll
    for (int mi = 0; mi < 4; mi++)
#pragma unroll
      for (int ni = 0; ni < 2; ni++)
#pragma unroll
        for (int ep2 = 0; ep2 < 2; ep2++) {
          int row = wm * 64 + mi * 16 + (lane >> 2) + ep2 * 8;  // token local
          int j0 = wn * 16 + ni * 8 + (lane & 3) * 2;           // even; rope bands don't straddle
          int gtoken = (int)bm + row;
          int p;
          if constexpr (MODE == 0) {
            int t = gtoken >> 8, rem = gtoken & 255;
            p = (j0 < 16) ? c_tmap[t] : (j0 < 40) ? 2 * (rem >> 4) + 1 : 2 * (rem & 15) + 1;
          } else {
            p = (j0 < 16) ? (gtoken >> 10) : (j0 < 40) ? ((gtoken >> 5) & 31) : (gtoken & 31);
          }
          float oa0, oa1, ob0, ob1;
#pragma unroll
          for (int sub = 0; sub < 2; sub++) {
            int j = j0 + sub;
            float x0 = acc[mi][ni][2 * ep2 + sub] + bias[h * HD + j];
            float x1 = acc[mi][ni + 2][2 * ep2 + sub] + bias[h * HD + j + 64];
            float invf = ex2f(-(float)j * 0.20762050593046015f);  // 10000^(-j/64)
            float ang = (float)p * invf;
            ang -= 6.283185307179586f * floorf(ang * 0.15915494309189535f);
            float sv, cv;
            __sincosf(ang, &sv, &cv);
            float o0 = x0 * cv - x1 * sv, o1 = x1 * cv + x0 * sv;
            if constexpr (MODE == 0) { o0 *= CSC; o1 *= CSC; }
            if (sub == 0) { oa0 = o0; oa1 = o1; } else { ob0 = o0; ob1 = o1; }
          }
          *(__half2*)&ep[row * EROW + j0]      = __floats2half2_rn(oa0, ob0);
          *(__half2*)&ep[row * EROW + j0 + 64] = __floats2half2_rn(oa1, ob1);
        }
  }
  __syncthreads();

  // coalesced copy out: 128 rows x 256B, int4 granules
#pragma unroll
  for (int i = 0; i < 8; i++) {
    int idx = tid + i * 256;
    int row = idx >> 4;             // 16 int4 per row
    int col = (idx & 15) * 8;       // halves
    int4 val = *(const int4*)&ep[row * EROW + col];
    if constexpr (MODE == 2) {
      int tg = (int)(bm >> 12);
      size_t dst = ((size_t)(tg * NH + h) * HD + row) * LK + (bm & 4095) + col;
      *(int4*)&g_VhT[dst] = val;
    } else {
      int gtoken = (int)bm + row;
      size_t base;
      if constexpr (MODE == 0) {
        int t = gtoken >> 8, rem = gtoken & 255;
        base = ((size_t)(t * NH + h) * SQ + rem) * HD;
      } else {
        base = ((size_t)((gtoken >> 12) * NH + h) * LK + (gtoken & 4095)) * HD;
      }
      __half* dst = (MODE == 0) ? g_Qh : g_Kh;
      *(int4*)&dst[base + col] = val;
    }
  }
}

// ---------------- flash attention (unchanged, passing since round 6) ----------------
static constexpr int FPAD = 136;
static constexpr int FLASH_SMEM = 5 * 128 * FPAD * 2;

__global__ void __launch_bounds__(256, 1) k_flash(float* __restrict__ out) {
  extern __shared__ __half fsm[];
  __half* Qs = fsm;
  __half* Ks = fsm + 128 * FPAD;
  __half* Vs = fsm + 3 * 128 * FPAD;

  const int bz = blockIdx.y;
  const int q0 = blockIdx.x * 128;
  const int tid = threadIdx.x, lane = tid & 31, warp = tid >> 5;
  const int r0w = warp * 16;
  const __half* Qg = g_Qh + ((size_t)bz * SQ + q0) * HD;
  const __half* Kg = g_Kh + (size_t)bz * LK * HD;
  const __half* Vg = g_VhT + (size_t)bz * HD * LK;

  auto load_kv = [&](int j, int s) {
    const __half* kg = Kg + (size_t)j * 128 * HD;
#pragma unroll
    for (int i = 0; i < 8; i++) {
      int idx = tid + i * 256; int r = idx >> 4, c = (idx & 15) * 8;
      cp16(Ks + (size_t)s * 128 * FPAD + r * FPAD + c, kg + (size_t)r * HD + c);
    }
#pragma unroll
    for (int i = 0; i < 8; i++) {
      int idx = tid + i * 256; int r = idx >> 4, c = (idx & 15) * 8;
      cp16(Vs + (size_t)s * 128 * FPAD + r * FPAD + c, Vg + (size_t)r * LK + j * 128 + c);
    }
    cp_commit();
  };

#pragma unroll
  for (int i = 0; i < 8; i++) {
    int idx = tid + i * 256; int r = idx >> 4, c = (idx & 15) * 8;
    cp16(Qs + r * FPAD + c, Qg + (size_t)r * HD + c);
  }
  load_kv(0, 0);
  load_kv(1, 1);

  float o[16][4];
#pragma unroll
  for (int f = 0; f < 16; f++)
#pragma unroll
    for (int e = 0; e < 4; e++) o[f][e] = 0.f;
  float mlo = -1e30f, mhi = -1e30f, llo = 0.f, lhi = 0.f;

  for (int j = 0; j < 32; j++) {
    if (j + 1 < 32) cp_wait<1>(); else cp_wait<0>();
    __syncthreads();
    const int s = j & 1;
    const __half* KsS = Ks + (size_t)s * 128 * FPAD;
    const __half* VsS = Vs + (size_t)s * 128 * FPAD;

    float sfr[16][4];
#pragma unroll
    for (int f = 0; f < 16; f++)
#pragma unroll
      for (int e = 0; e < 4; e++) sfr[f][e] = 0.f;
#pragma unroll
    for (int ks = 0; ks < 8; ks++) {
      unsigned a[4];
      ldsm4(a, Qs + (r0w + ((lane >> 3) & 1) * 8 + (lane & 7)) * FPAD + ks * 16 + (lane >> 4) * 8);
#pragma unroll
      for (int f = 0; f < 8; f++) {
        unsigned b[4];
        ldsm4(b, KsS + (f * 16 + (lane >> 4) * 8 + (lane & 7)) * FPAD + ks * 16 + ((lane >> 3) & 1) * 8);
        mma16816(sfr[2 * f], a, b);
        mma16816(sfr[2 * f + 1], a, b + 2);
      }
    }

    float cmlo = -1e30f, cmhi = -1e30f;
#pragma unroll
    for (int f = 0; f < 16; f++) {
      cmlo = fmaxf(cmlo, fmaxf(sfr[f][0], sfr[f][1]));
      cmhi = fmaxf(cmhi, fmaxf(sfr[f][2], sfr[f][3]));
    }
#pragma unroll
    for (int ofs = 1; ofs < 4; ofs <<= 1) {
      cmlo = fmaxf(cmlo, __shfl_xor_sync(0xffffffffu, cmlo, ofs));
      cmhi = fmaxf(cmhi, __shfl_xor_sync(0xffffffffu, cmhi, ofs));
    }
    float mnlo = fmaxf(mlo, cmlo), mnhi = fmaxf(mhi, cmhi);
    float alo = ex2f(mlo - mnlo), ahi = ex2f(mhi - mnhi);
    mlo = mnlo; mhi = mnhi;

    unsigned pa[8][4];
    float slo = 0.f, shi = 0.f;
#pragma unroll
    for (int f = 0; f < 16; f++) {
      __half2 dlo = __floats2half2_rn(sfr[f][0] - mnlo, sfr[f][1] - mnlo);
      __half2 dhi = __floats2half2_rn(sfr[f][2] - mnhi, sfr[f][3] - mnhi);
      unsigned plo = h2ex2(*(unsigned*)&dlo);
      unsigned phi = h2ex2(*(unsigned*)&dhi);
      int ks = f >> 1, half_ = (f & 1) * 2;
      pa[ks][half_ + 0] = plo;
      pa[ks][half_ + 1] = phi;
      float2 flo = __half22float2(*(__half2*)&plo);
      float2 fhi = __half22float2(*(__half2*)&phi);
      slo += flo.x + flo.y;
      shi += fhi.x + fhi.y;
    }
#pragma unroll
    for (int ofs = 1; ofs < 4; ofs <<= 1) {
      slo += __shfl_xor_sync(0xffffffffu, slo, ofs);
      shi += __shfl_xor_sync(0xffffffffu, shi, ofs);
    }
    llo = llo * alo + slo;
    lhi = lhi * ahi + shi;
#pragma unroll
    for (int f = 0; f < 16; f++) {
      o[f][0] *= alo; o[f][1] *= alo;
      o[f][2] *= ahi; o[f][3] *= ahi;
    }

#pragma unroll
    for (int ks = 0; ks < 8; ks++) {
#pragma unroll
      for (int f = 0; f < 8; f++) {
        unsigned b[4];
        ldsm4(b, VsS + (f * 16 + (lane >> 4) * 8 + (lane & 7)) * FPAD + ks * 16 + ((lane >> 3) & 1) * 8);
        mma16816(o[2 * f], pa[ks], b);
        mma16816(o[2 * f + 1], pa[ks], b + 2);
      }
    }
    __syncthreads();
    if (j + 2 < 32) load_kv(j + 2, s);
  }

  float ilo = 1.0f / llo, ihi = 1.0f / lhi;
  int t = bz >> 3, h = bz & 7;
  size_t rowbase = ((size_t)t * SQ + q0 + r0w + (lane >> 2)) * DM + (size_t)h * HD;
#pragma unroll
  for (int f = 0; f < 16; f++) {
    int c = f * 8 + (lane & 3) * 2;
    *(float2*)&out[rowbase + c] = make_float2(o[f][0] * ilo, o[f][1] * ilo);
    *(float2*)&out[rowbase + 8 * DM + c] = make_float2(o[f][2] * ihi, o[f][3] * ihi);
  }
}

// ---------------- input cast fp32 -> fp16 (dst via sel_ptr, device-resolved) ----------------
template<int DSEL>
__global__ void k_cast(const float* __restrict__ s) {
  __half* __restrict__ d = sel_ptr<DSEL>();
  size_t i = ((size_t)blockIdx.x * blockDim.x + threadIdx.x) * 8;
  float4 f0 = *(const float4*)(s + i);
  float4 f1 = *(const float4*)(s + i + 4);
  __half2 h[4];
  h[0] = __floats2half2_rn(f0.x, f0.y);
  h[1] = __floats2half2_rn(f0.z, f0.w);
  h[2] = __floats2half2_rn(f1.x, f1.y);
  h[3] = __floats2half2_rn(f1.z, f1.w);
  *(int4*)(d + i) = *(const int4*)h;
}

// ---------------- weight transpose+cast (smem-tiled) ----------------
__global__ void k_prep_w(const float* __restrict__ Wq, const float* __restrict__ Wk,
                         const float* __restrict__ Wv) {
  __shared__ float ts[3][32][33];
  const int bo = blockIdx.x * 32;
  const int bi = blockIdx.y * 32;
  const int tx = threadIdx.x, ty = threadIdx.y;  // (32, 8)
#pragma unroll
  for (int i = 0; i < 32; i += 8) {
    int src = (bi + ty + i) * DM + bo + tx;
    ts[0][ty + i][tx] = Wq[src];
    ts[1][ty + i][tx] = Wk[src];
    ts[2][ty + i][tx] = Wv[src];
  }
  __syncthreads();
#pragma unroll
  for (int i = 0; i < 32; i += 8) {
    int dst = (bo + ty + i) * DM + bi + tx;
    g_Wt[0][dst] = __float2half(ts[0][tx][ty + i]);
    g_Wt[1][dst] = __float2half(ts[1][tx][ty + i]);
    g_Wt[2][dst] = __float2half(ts[2][tx][ty + i]);
  }
}

// ---------------- launch ----------------
extern "C" void kernel_launch(void* const* d_in, const int* in_sizes, int n_in,
                              void* d_out, int out_size) {
  const float* q  = (const float*)d_in[0];
  const float* k  = (const float*)d_in[1];
  const float* v  = (const float*)d_in[2];
  const float* Wq = (const float*)d_in[3];
  const float* bq = (const float*)d_in[4];
  const float* Wk = (const float*)d_in[5];
  const float* bk = (const float*)d_in[6];
  const float* Wv = (const float*)d_in[7];
  const float* bv = (const float*)d_in[8];
  float* out = (float*)d_out;
  (void)in_sizes; (void)n_in; (void)out_size;

  cudaFuncSetAttribute(k_flash, cudaFuncAttributeMaxDynamicSharedMemorySize, FLASH_SMEM);
  cudaFuncSetAttribute(k_gemm3<0, 3, 0>, cudaFuncAttributeMaxDynamicSharedMemorySize, PROJ_SMEM);
  cudaFuncSetAttribute(k_gemm3<1, 4, 1>, cudaFuncAttributeMaxDynamicSharedMemorySize, PROJ_SMEM);
  cudaFuncSetAttribute(k_gemm3<2, 5, 2>, cudaFuncAttributeMaxDynamicSharedMemorySize, PROJ_SMEM);

  k_cast<3><<<(NQ * DM) / 2048, 256>>>(q);
  k_cast<4><<<(NK * DM) / 2048, 256>>>(k);
  k_cast<5><<<(NK * DM) / 2048, 256>>>(v);
  k_prep_w<<<dim3(32, 32), dim3(32, 8)>>>(Wq, Wk, Wv);

  // projections with fused bias + rope + layout epilogues (smem-staged stores)
  k_gemm3<0, 3, 0><<<dim3(NH, NQ / 128), 256, PROJ_SMEM>>>(bq);
  k_gemm3<1, 4, 1><<<dim3(NH, NK / 128), 256, PROJ_SMEM>>>(bk);
  k_gemm3<2, 5, 2><<<dim3(NH, NK / 128), 256, PROJ_SMEM>>>(bv);

  // fused attention
  k_flash<<<dim3(2, 64), 256, FLASH_SMEM>>>(out);
}